// round 5
// baseline (speedup 1.0000x reference)
#include <cuda_runtime.h>
#include <math.h>

#define T_STEPS 512
#define BATCH   256
#define OBSD    256
#define HIDD    512
#define LSTMD   512
#define ACTD    32
#define ROWS    (T_STEPS * BATCH)   /* 131072 */
#define GATES_N (4 * LSTMD)         /* 2048 */
#define HT_ELEMS (BATCH * LSTMD)    /* 131072 */
#define NBLK     128

// ---------------- scratch (static device globals; no runtime allocation) ----
__device__ float    g_xr   [(size_t)ROWS * OBSD];          // tf32-rounded x
__device__ float    g_WencR[(size_t)OBSD * HIDD];          // tf32-rounded W_enc
__device__ float    g_feats[(size_t)ROWS * HIDD];          // tf32-rounded feats
__device__ float    g_gates[(size_t)ROWS * GATES_N];       // permuted 4j+g
__device__ float    g_ys   [(size_t)ROWS * LSTMD];
__device__ float    g_hT   [2 * HT_ELEMS];                 // ping-pong h (tf32)
__device__ float    g_WiP  [(size_t)HIDD * GATES_N];       // permuted+rounded W_i
__device__ unsigned g_WhP  [(size_t)LSTMD * GATES_N];      // permuted W_h (tf32)
__device__ float    g_bP   [GATES_N];                      // permuted b_lstm
__device__ unsigned g_flags[NBLK];                         // barrier flags

__device__ __forceinline__ float gelu_f(float x) {
    float x3 = x * x * x;
    float t  = tanhf(0.7978845608028654f * (x + 0.044715f * x3));
    return 0.5f * x * (1.0f + t);
}
__device__ __forceinline__ float sigm(float x) { return 1.0f / (1.0f + expf(-x)); }

__device__ __forceinline__ unsigned f2tf32(float x) {
    unsigned u;
    asm("cvt.rna.tf32.f32 %0, %1;" : "=r"(u) : "f"(x));
    return u;
}

__device__ __forceinline__ void mma_tf32(float c[4],
                                         unsigned a0, unsigned a1, unsigned a2, unsigned a3,
                                         unsigned b0, unsigned b1) {
    asm volatile(
        "mma.sync.aligned.m16n8k8.row.col.f32.tf32.tf32.f32 "
        "{%0,%1,%2,%3}, {%4,%5,%6,%7}, {%8,%9}, {%0,%1,%2,%3};\n"
        : "+f"(c[0]), "+f"(c[1]), "+f"(c[2]), "+f"(c[3])
        : "r"(a0), "r"(a1), "r"(a2), "r"(a3), "r"(b0), "r"(b1));
}

__device__ __forceinline__ void cp16(void* smem_dst, const void* gsrc) {
    unsigned d = (unsigned)__cvta_generic_to_shared(smem_dst);
    asm volatile("cp.async.ca.shared.global [%0], [%1], 16;\n" :: "r"(d), "l"(gsrc));
}
__device__ __forceinline__ void cp16cg(void* smem_dst, const void* gsrc) {
    unsigned d = (unsigned)__cvta_generic_to_shared(smem_dst);
    asm volatile("cp.async.cg.shared.global [%0], [%1], 16;\n" :: "r"(d), "l"(gsrc));
}
__device__ __forceinline__ void cp_commit() {
    asm volatile("cp.async.commit_group;\n");
}
template <int N>
__device__ __forceinline__ void cp_wait() {
    asm volatile("cp.async.wait_group %0;\n" :: "n"(N));
}

// ---------------- small utility kernels -------------------------------------
__global__ void zero_kernel(float* p, int n) {
    int i = blockIdx.x * blockDim.x + threadIdx.x;
    if (i < n) p[i] = 0.0f;
}
__global__ void zero_flags() {
    if (threadIdx.x < NBLK) g_flags[threadIdx.x] = 0u;
}

__global__ void round4_kernel(const float4* __restrict__ in,
                              float4* __restrict__ out, int n4) {
    int i = blockIdx.x * blockDim.x + threadIdx.x;
    if (i < n4) {
        float4 v = in[i];
        v.x = __uint_as_float(f2tf32(v.x));
        v.y = __uint_as_float(f2tf32(v.y));
        v.z = __uint_as_float(f2tf32(v.z));
        v.w = __uint_as_float(f2tf32(v.w));
        out[i] = v;
    }
}

// Wp[k][4j+g] = round(W[k][g*512+j])
__global__ void permute_wi(const float* __restrict__ W, float* __restrict__ Wp) {
    int idx = blockIdx.x * 256 + threadIdx.x;
    int k = idx >> 11, c = idx & 2047;
    Wp[idx] = __uint_as_float(f2tf32(W[(size_t)k * GATES_N + (c & 3) * LSTMD + (c >> 2)]));
}
__global__ void permute_wh(const float* __restrict__ W, unsigned* __restrict__ Wp) {
    int idx = blockIdx.x * 256 + threadIdx.x;
    int k = idx >> 11, c = idx & 2047;
    Wp[idx] = f2tf32(W[(size_t)k * GATES_N + (c & 3) * LSTMD + (c >> 2)]);
}
__global__ void permute_b(const float* __restrict__ b, float* __restrict__ bp) {
    int idx = blockIdx.x * 256 + threadIdx.x;
    if (idx < GATES_N) bp[idx] = b[(idx & 3) * LSTMD + (idx >> 2)];
}

// ---------------- big GEMM: C = act(A @ B + bias), cp.async double-buffered -
#define GA_STRIDE 36
#define GB_STRIDE 136
#define GA_ELEMS  (128 * GA_STRIDE)
#define GB_ELEMS  (32 * GB_STRIDE)
#define SMEM_GEMM ((2 * GA_ELEMS + 2 * GB_ELEMS) * 4)

__global__ void __launch_bounds__(256)
gemm_mma(const float* __restrict__ A,
         const float* __restrict__ B,
         const float* __restrict__ bias,
         float* __restrict__ C,
         int M, int N, int K, int do_gelu, int do_round)
{
    extern __shared__ unsigned gsm[];
    unsigned* As = gsm;
    unsigned* Bs = gsm + 2 * GA_ELEMS;

    const int bm = blockIdx.y * 128;
    const int bn = blockIdx.x * 128;
    const int tid  = threadIdx.x;
    const int warp = tid >> 5;
    const int lane = tid & 31;
    const int wm = (warp & 1) * 64;
    const int wn = (warp >> 1) * 32;
    const int r  = lane >> 2;
    const int q  = lane & 3;

    float acc[4][4][4];
#pragma unroll
    for (int mt = 0; mt < 4; mt++)
#pragma unroll
        for (int nt = 0; nt < 4; nt++)
#pragma unroll
            for (int i = 0; i < 4; i++) acc[mt][nt][i] = 0.0f;

    const float* Ab = A + (size_t)bm * K;
    const int nK = K >> 5;

    auto load_stage = [&](int kt, int buf) {
        unsigned* Ad = As + buf * GA_ELEMS;
        unsigned* Bd = Bs + buf * GB_ELEMS;
        int k0 = kt * 32;
#pragma unroll
        for (int it = 0; it < 4; it++) {
            int i  = tid + it * 256;
            int m  = i >> 3;
            int kq = (i & 7) * 4;
            cp16(&Ad[m * GA_STRIDE + kq], Ab + (size_t)m * K + k0 + kq);
        }
#pragma unroll
        for (int it = 0; it < 4; it++) {
            int i  = tid + it * 256;
            int kr = i >> 5;
            int nq = (i & 31) * 4;
            cp16(&Bd[kr * GB_STRIDE + nq], B + (size_t)(k0 + kr) * N + bn + nq);
        }
        cp_commit();
    };

    load_stage(0, 0);

    for (int kt = 0; kt < nK; kt++) {
        if (kt + 1 < nK) { load_stage(kt + 1, (kt + 1) & 1); cp_wait<1>(); }
        else             { cp_wait<0>(); }
        __syncthreads();

        const unsigned* Ac = As + (kt & 1) * GA_ELEMS;
        const unsigned* Bc = Bs + (kt & 1) * GB_ELEMS;
#pragma unroll
        for (int kk = 0; kk < 32; kk += 8) {
            unsigned af[4][4], bf[4][2];
#pragma unroll
            for (int mt = 0; mt < 4; mt++) {
                int mb = wm + mt * 16;
                af[mt][0] = Ac[(mb + r    ) * GA_STRIDE + kk + q];
                af[mt][1] = Ac[(mb + r + 8) * GA_STRIDE + kk + q];
                af[mt][2] = Ac[(mb + r    ) * GA_STRIDE + kk + q + 4];
                af[mt][3] = Ac[(mb + r + 8) * GA_STRIDE + kk + q + 4];
            }
#pragma unroll
            for (int nt = 0; nt < 4; nt++) {
                int nb = wn + nt * 8 + r;
                bf[nt][0] = Bc[(kk + q    ) * GB_STRIDE + nb];
                bf[nt][1] = Bc[(kk + q + 4) * GB_STRIDE + nb];
            }
#pragma unroll
            for (int mt = 0; mt < 4; mt++)
#pragma unroll
                for (int nt = 0; nt < 4; nt++)
                    mma_tf32(acc[mt][nt], af[mt][0], af[mt][1], af[mt][2], af[mt][3],
                             bf[nt][0], bf[nt][1]);
        }
        __syncthreads();
    }

#pragma unroll
    for (int mt = 0; mt < 4; mt++) {
#pragma unroll
        for (int nt = 0; nt < 4; nt++) {
            int row = bm + wm + mt * 16 + r;
            int col = bn + wn + nt * 8 + 2 * q;
            float b0 = bias[col], b1 = bias[col + 1];
            float z00 = acc[mt][nt][0] + b0, z01 = acc[mt][nt][1] + b1;
            float z10 = acc[mt][nt][2] + b0, z11 = acc[mt][nt][3] + b1;
            if (do_gelu) {
                z00 = gelu_f(z00); z01 = gelu_f(z01);
                z10 = gelu_f(z10); z11 = gelu_f(z11);
            }
            if (do_round) {
                z00 = __uint_as_float(f2tf32(z00));
                z01 = __uint_as_float(f2tf32(z01));
                z10 = __uint_as_float(f2tf32(z10));
                z11 = __uint_as_float(f2tf32(z11));
            }
            *reinterpret_cast<float2*>(C + (size_t)row * N + col) =
                make_float2(z00, z01);
            *reinterpret_cast<float2*>(C + (size_t)(row + 8) * N + col) =
                make_float2(z10, z11);
        }
    }
}

// ---------------- persistent fused LSTM recurrence --------------------------
// 128 blocks (32 j-tiles x 4 batch-tiles of 64 rows), weight-stationary,
// BK=128 double-buffered h via cp.async.cg, flag-array grid barrier.
#define WS_STRIDE 72
#define AS_STRIDE 132
#define WS_ELEMS  (LSTMD * WS_STRIDE)          /* 36864 u32 = 144KB */
#define AS_ELEMS  (64 * AS_STRIDE)             /* 8448 u32 = 33KB per buf */
#define CS_STRIDE 17
#define SMEM_LSTM ((WS_ELEMS + 2 * AS_ELEMS) * 4 + 64 * CS_STRIDE * 4)

__global__ void __launch_bounds__(256, 1)
lstm_persistent(const unsigned* __restrict__ Wp,
                const float* __restrict__ gates,
                float* __restrict__ ys)
{
    extern __shared__ unsigned smem[];
    unsigned* Ws  = smem;                          // [512][72]
    unsigned* As0 = smem + WS_ELEMS;               // [2][64][132]
    float*    Cs  = (float*)(smem + WS_ELEMS + 2 * AS_ELEMS);  // [64][17]

    const int jt = blockIdx.x;          // 0..31
    const int bt = blockIdx.y;          // 0..3
    const int bn = jt * 64;
    const int bm = bt * 64;
    const int bid = bt * 32 + jt;
    const int tid  = threadIdx.x;
    const int warp = tid >> 5;
    const int lane = tid & 31;
    const int wm = (warp & 1) * 32;
    const int wn = (warp >> 1) * 16;
    const int r  = lane >> 2;
    const int q  = lane & 3;
    const int p  = q & 1;

    for (int i = tid; i < LSTMD * 16; i += 256) {
        int k  = i >> 4;
        int nq = (i & 15) * 4;
        uint4 v = *reinterpret_cast<const uint4*>(Wp + (size_t)k * GATES_N + bn + nq);
        *reinterpret_cast<uint4*>(&Ws[k * WS_STRIDE + nq]) = v;
    }
    for (int i = tid; i < 64 * CS_STRIDE; i += 256) Cs[i] = 0.0f;
    __syncthreads();

    // preload gx for t=0
    float2 gxc[2][2][2];
    {
        const float* gx = gates;
#pragma unroll
        for (int mt = 0; mt < 2; mt++)
#pragma unroll
            for (int nt = 0; nt < 2; nt++) {
                int row = bm + wm + mt * 16 + r;
                int col = bn + wn + nt * 8 + 2 * q;
                gxc[mt][nt][0] = *reinterpret_cast<const float2*>(
                    gx + (size_t)row * GATES_N + col);
                gxc[mt][nt][1] = *reinterpret_cast<const float2*>(
                    gx + (size_t)(row + 8) * GATES_N + col);
            }
    }

    for (int t = 0; t < T_STEPS; t++) {
        const float* hin  = g_hT + ((t & 1) ? HT_ELEMS : 0);
        float*       hout = g_hT + ((t & 1) ? 0 : HT_ELEMS);

        float acc[2][2][4];
#pragma unroll
        for (int mt = 0; mt < 2; mt++)
#pragma unroll
            for (int nt = 0; nt < 2; nt++)
#pragma unroll
                for (int i = 0; i < 4; i++) acc[mt][nt][i] = 0.0f;

        // prefetch chunk 0 (64 rows x 128 k), L2-only
        {
            unsigned* A = As0;
#pragma unroll
            for (int it = 0; it < 8; it++) {
                int i  = tid + it * 256;
                int m  = i >> 5;
                int kq = (i & 31) * 4;
                cp16cg(&A[m * AS_STRIDE + kq], hin + (size_t)(bm + m) * LSTMD + kq);
            }
            cp_commit();
        }

        // prefetch gx for step t+1 (independent of barrier; hides DRAM latency)
        float2 gxn[2][2][2];
        {
            int tn = (t + 1 < T_STEPS) ? (t + 1) : t;
            const float* gx = gates + (size_t)tn * BATCH * GATES_N;
#pragma unroll
            for (int mt = 0; mt < 2; mt++)
#pragma unroll
                for (int nt = 0; nt < 2; nt++) {
                    int row = bm + wm + mt * 16 + r;
                    int col = bn + wn + nt * 8 + 2 * q;
                    gxn[mt][nt][0] = *reinterpret_cast<const float2*>(
                        gx + (size_t)row * GATES_N + col);
                    gxn[mt][nt][1] = *reinterpret_cast<const float2*>(
                        gx + (size_t)(row + 8) * GATES_N + col);
                }
        }

        for (int c = 0; c < 4; c++) {
            if (c < 3) {
                unsigned* A = As0 + ((c + 1) & 1) * AS_ELEMS;
                int kb = (c + 1) * 128;
#pragma unroll
                for (int it = 0; it < 8; it++) {
                    int i  = tid + it * 256;
                    int m  = i >> 5;
                    int kq = (i & 31) * 4;
                    cp16cg(&A[m * AS_STRIDE + kq],
                           hin + (size_t)(bm + m) * LSTMD + kb + kq);
                }
                cp_commit();
                cp_wait<1>();
            } else {
                cp_wait<0>();
            }
            __syncthreads();

            const unsigned* A = As0 + (c & 1) * AS_ELEMS;
            const int kbase = c * 128;
#pragma unroll
            for (int kk = 0; kk < 128; kk += 8) {
                unsigned af[2][4], bf[2][2];
#pragma unroll
                for (int mt = 0; mt < 2; mt++) {
                    int mb = wm + mt * 16;
                    af[mt][0] = A[(mb + r    ) * AS_STRIDE + kk + q];
                    af[mt][1] = A[(mb + r + 8) * AS_STRIDE + kk + q];
                    af[mt][2] = A[(mb + r    ) * AS_STRIDE + kk + q + 4];
                    af[mt][3] = A[(mb + r + 8) * AS_STRIDE + kk + q + 4];
                }
#pragma unroll
                for (int nt = 0; nt < 2; nt++) {
                    int nc = wn + nt * 8 + r;
                    bf[nt][0] = Ws[(kbase + kk + q    ) * WS_STRIDE + nc];
                    bf[nt][1] = Ws[(kbase + kk + q + 4) * WS_STRIDE + nc];
                }
#pragma unroll
                for (int mt = 0; mt < 2; mt++)
#pragma unroll
                    for (int nt = 0; nt < 2; nt++)
                        mma_tf32(acc[mt][nt], af[mt][0], af[mt][1], af[mt][2], af[mt][3],
                                 bf[nt][0], bf[nt][1]);
            }
            __syncthreads();
        }

        // epilogue: gates + cell update
        float* yst = ys + (size_t)t * BATCH * LSTMD;
#pragma unroll
        for (int mt = 0; mt < 2; mt++) {
#pragma unroll
            for (int nt = 0; nt < 2; nt++) {
                int lrow = wm + mt * 16 + r;
                int lcol = wn + nt * 8 + 2 * q;
                float z00 = acc[mt][nt][0] + gxc[mt][nt][0].x;
                float z01 = acc[mt][nt][1] + gxc[mt][nt][0].y;
                float z10 = acc[mt][nt][2] + gxc[mt][nt][1].x;
                float z11 = acc[mt][nt][3] + gxc[mt][nt][1].y;

                float u0a = (p == 0) ? sigm(z00) : tanhf(z00);
                float u1a = sigm(z01);
                float u0b = (p == 0) ? sigm(z10) : tanhf(z10);
                float u1b = sigm(z11);

                float v0a = __shfl_xor_sync(0xffffffffu, u0a, 1);
                float v1a = __shfl_xor_sync(0xffffffffu, u1a, 1);
                float v0b = __shfl_xor_sync(0xffffffffu, u0b, 1);
                float v1b = __shfl_xor_sync(0xffffffffu, u1b, 1);

                if (p == 0) {
                    int jl = lcol >> 2;
                    int jg = jt * 16 + jl;
                    {
                        float co = Cs[lrow * CS_STRIDE + jl];
                        float cn = u1a * co + u0a * v0a;
                        Cs[lrow * CS_STRIDE + jl] = cn;
                        float h = v1a * tanhf(cn);
                        size_t gi = (size_t)(bm + lrow) * LSTMD + jg;
                        yst[gi]  = h;
                        hout[gi] = __uint_as_float(f2tf32(h));
                    }
                    {
                        int lr2 = lrow + 8;
                        float co = Cs[lr2 * CS_STRIDE + jl];
                        float cn = u1b * co + u0b * v0b;
                        Cs[lr2 * CS_STRIDE + jl] = cn;
                        float h = v1b * tanhf(cn);
                        size_t gi = (size_t)(bm + lr2) * LSTMD + jg;
                        yst[gi]  = h;
                        hout[gi] = __uint_as_float(f2tf32(h));
                    }
                }
            }
        }

        // carry gx
#pragma unroll
        for (int mt = 0; mt < 2; mt++)
#pragma unroll
            for (int nt = 0; nt < 2; nt++) {
                gxc[mt][nt][0] = gxn[mt][nt][0];
                gxc[mt][nt][1] = gxn[mt][nt][1];
            }

        // flag-array grid barrier (no atomic serialization)
        __syncthreads();
        unsigned tgt = (unsigned)(t + 1);
        if (tid == 0) {
            __threadfence();
            asm volatile("st.release.gpu.u32 [%0], %1;"
                         :: "l"(&g_flags[bid]), "r"(tgt) : "memory");
        }
        if (tid < NBLK) {
            unsigned v;
            for (;;) {
                asm volatile("ld.acquire.gpu.u32 %0, [%1];"
                             : "=r"(v) : "l"(&g_flags[tid]) : "memory");
                if (v >= tgt) break;
                __nanosleep(32);
            }
        }
        __syncthreads();
    }
}

// ---------------- heads: mu+sigma (smem-tiled), value (warp/row) ------------
// mu kernel: block = 256 threads handles 128 rows; Wmu resident in smem;
// y chunk staged transposed so inner loop reads LDS.128.
#define MU_SMEM (512 * 32 * 4 + 32 * 132 * 4)   /* 64KB + 16.5KB */

__global__ void __launch_bounds__(256)
mu_kernel(const float* __restrict__ Wmu,
          const float* __restrict__ bmu,
          const float* __restrict__ logstd,
          float* __restrict__ out)
{
    extern __shared__ float msm[];
    float* Wsm = msm;                 // [512][32]
    float* Ytr = msm + 512 * 32;      // [32][132]

    const int tid = threadIdx.x;
    const int tx = tid & 31;          // action
    const int ty = tid >> 5;          // 0..7 (row group)
    const size_t row0 = (size_t)blockIdx.x * 128;
    const float* yb = g_ys + row0 * LSTMD;

    for (int i = tid; i < 512 * 32 / 4; i += 256)
        *reinterpret_cast<float4*>(Wsm + i * 4) =
            *reinterpret_cast<const float4*>(Wmu + i * 4);

    float acc[16];
#pragma unroll
    for (int i = 0; i < 16; i++) acc[i] = 0.0f;

    for (int k0 = 0; k0 < LSTMD; k0 += 32) {
        __syncthreads();
#pragma unroll
        for (int it = 0; it < 4; it++) {
            int idx = tid + it * 256;         // 1024 float4 = 128 rows x 8
            int rr = idx >> 3;
            int f  = idx & 7;
            float4 v = *reinterpret_cast<const float4*>(
                yb + (size_t)rr * LSTMD + k0 + f * 4);
            Ytr[(f * 4 + 0) * 132 + rr] = v.x;
            Ytr[(f * 4 + 1) * 132 + rr] = v.y;
            Ytr[(f * 4 + 2) * 132 + rr] = v.z;
            Ytr[(f * 4 + 3) * 132 + rr] = v.w;
        }
        __syncthreads();

#pragma unroll
        for (int kk = 0; kk < 32; kk++) {
            float w = Wsm[(k0 + kk) * 32 + tx];
            const float4* yv = reinterpret_cast<const float4*>(
                &Ytr[kk * 132 + ty * 16]);
            float4 y0 = yv[0], y1 = yv[1], y2 = yv[2], y3 = yv[3];
            acc[0]  = fmaf(y0.x, w, acc[0]);  acc[1]  = fmaf(y0.y, w, acc[1]);
            acc[2]  = fmaf(y0.z, w, acc[2]);  acc[3]  = fmaf(y0.w, w, acc[3]);
            acc[4]  = fmaf(y1.x, w, acc[4]);  acc[5]  = fmaf(y1.y, w, acc[5]);
            acc[6]  = fmaf(y1.z, w, acc[6]);  acc[7]  = fmaf(y1.w, w, acc[7]);
            acc[8]  = fmaf(y2.x, w, acc[8]);  acc[9]  = fmaf(y2.y, w, acc[9]);
            acc[10] = fmaf(y2.z, w, acc[10]); acc[11] = fmaf(y2.w, w, acc[11]);
            acc[12] = fmaf(y3.x, w, acc[12]); acc[13] = fmaf(y3.y, w, acc[13]);
            acc[14] = fmaf(y3.z, w, acc[14]); acc[15] = fmaf(y3.w, w, acc[15]);
        }
    }

    float* mu    = out;
    float* sigma = out + (size_t)ROWS * ACTD;
    float bb = bmu[tx];
    float sg = expf(logstd[tx]);
#pragma unroll
    for (int i = 0; i < 16; i++) {
        size_t row = row0 + ty * 16 + i;
        mu[row * ACTD + tx]    = acc[i] + bb;
        sigma[row * ACTD + tx] = sg;
    }
}

__global__ void __launch_bounds__(256)
value_kernel(const float* __restrict__ Wv,
             const float* __restrict__ bv,
             float* __restrict__ out)
{
    const int lane = threadIdx.x & 31;
    const size_t row = (size_t)blockIdx.x * 8 + (threadIdx.x >> 5);
    const float* yrow = g_ys + row * LSTMD;

    float v = 0.0f;
#pragma unroll
    for (int pass = 0; pass < 4; pass++) {
        int k = pass * 128 + lane * 4;
        float4 y = *reinterpret_cast<const float4*>(yrow + k);
        float4 w = *reinterpret_cast<const float4*>(Wv + k);
        v = fmaf(y.x, w.x, v); v = fmaf(y.y, w.y, v);
        v = fmaf(y.z, w.z, v); v = fmaf(y.w, w.w, v);
    }
#pragma unroll
    for (int o = 16; o; o >>= 1) v += __shfl_xor_sync(0xffffffffu, v, o);
    if (lane == 0)
        out[(size_t)2 * ROWS * ACTD + row] = v + bv[0];
}

// ---------------- launch ----------------------------------------------------
extern "C" void kernel_launch(void* const* d_in, const int* in_sizes, int n_in,
                              void* d_out, int out_size)
{
    (void)in_sizes; (void)n_in; (void)out_size;
    const float* x      = (const float*)d_in[0];
    const float* W_enc  = (const float*)d_in[1];
    const float* b_enc  = (const float*)d_in[2];
    const float* W_i    = (const float*)d_in[3];
    const float* W_h    = (const float*)d_in[4];
    const float* b_lstm = (const float*)d_in[5];
    const float* W_mu   = (const float*)d_in[6];
    const float* b_mu   = (const float*)d_in[7];
    const float* logstd = (const float*)d_in[8];
    const float* W_v    = (const float*)d_in[9];
    const float* b_v    = (const float*)d_in[10];
    float* out = (float*)d_out;

    float *xr, *WencR, *feats, *gates, *ys, *hT, *WiP, *bP;
    unsigned* WhP;
    cudaGetSymbolAddress((void**)&xr,    g_xr);
    cudaGetSymbolAddress((void**)&WencR, g_WencR);
    cudaGetSymbolAddress((void**)&feats, g_feats);
    cudaGetSymbolAddress((void**)&gates, g_gates);
    cudaGetSymbolAddress((void**)&ys,    g_ys);
    cudaGetSymbolAddress((void**)&hT,    g_hT);
    cudaGetSymbolAddress((void**)&WiP,   g_WiP);
    cudaGetSymbolAddress((void**)&WhP,   g_WhP);
    cudaGetSymbolAddress((void**)&bP,    g_bP);

    static int attr_set = 0;
    if (!attr_set) {
        cudaFuncSetAttribute(lstm_persistent,
                             cudaFuncAttributeMaxDynamicSharedMemorySize, SMEM_LSTM);
        cudaFuncSetAttribute(gemm_mma,
                             cudaFuncAttributeMaxDynamicSharedMemorySize, SMEM_GEMM);
        cudaFuncSetAttribute(mu_kernel,
                             cudaFuncAttributeMaxDynamicSharedMemorySize, MU_SMEM);
        attr_set = 1;
    }

    zero_kernel<<<(HT_ELEMS + 255) / 256, 256>>>(hT, HT_ELEMS);
    zero_flags<<<1, 128>>>();

    round4_kernel<<<(ROWS * OBSD / 4 + 255) / 256, 256>>>(
        (const float4*)x, (float4*)xr, ROWS * OBSD / 4);
    round4_kernel<<<(OBSD * HIDD / 4 + 255) / 256, 256>>>(
        (const float4*)W_enc, (float4*)WencR, OBSD * HIDD / 4);
    permute_wi<<<(HIDD * GATES_N) / 256, 256>>>(W_i, WiP);
    permute_wh<<<(LSTMD * GATES_N) / 256, 256>>>(W_h, WhP);
    permute_b<<<(GATES_N + 255) / 256, 256>>>(b_lstm, bP);

    {
        dim3 grid(HIDD / 128, ROWS / 128);
        gemm_mma<<<grid, 256, SMEM_GEMM>>>(xr, WencR, b_enc, feats,
                                           ROWS, HIDD, OBSD, 1, 1);
    }
    {
        dim3 grid(GATES_N / 128, ROWS / 128);
        gemm_mma<<<grid, 256, SMEM_GEMM>>>(feats, WiP, bP, gates,
                                           ROWS, GATES_N, HIDD, 0, 0);
    }
    {
        dim3 grid(32, 4);
        lstm_persistent<<<grid, 256, SMEM_LSTM>>>(WhP, gates, ys);
    }
    mu_kernel<<<ROWS / 128, 256, MU_SMEM>>>(W_mu, b_mu, logstd, out);
    value_kernel<<<ROWS / 8, 256>>>(W_v, b_v, out);
}

// round 7
// speedup vs baseline: 1.3132x; 1.3132x over previous
#include <cuda_runtime.h>
#include <math.h>

#define T_STEPS 512
#define BATCH   256
#define OBSD    256
#define HIDD    512
#define LSTMD   512
#define ACTD    32
#define ROWS    (T_STEPS * BATCH)   /* 131072 */
#define GATES_N (4 * LSTMD)         /* 2048 */
#define HT_ELEMS (BATCH * LSTMD)    /* 131072 */
#define NBLK     128

// ---------------- scratch (static device globals; no runtime allocation) ----
__device__ float    g_xr   [(size_t)ROWS * OBSD];          // tf32-rounded x
__device__ float    g_WencR[(size_t)OBSD * HIDD];          // tf32-rounded W_enc
__device__ float    g_feats[(size_t)ROWS * HIDD];          // tf32-rounded feats
__device__ float    g_gates[(size_t)ROWS * GATES_N];       // permuted 4j+g
__device__ float    g_ys   [(size_t)ROWS * LSTMD];
__device__ float    g_hT   [2 * HT_ELEMS];                 // ping-pong h (tf32)
__device__ float    g_WiP  [(size_t)HIDD * GATES_N];       // permuted+rounded W_i
__device__ unsigned g_WhP  [(size_t)LSTMD * GATES_N];      // permuted W_h (tf32)
__device__ float    g_bP   [GATES_N];                      // permuted b_lstm
__device__ unsigned g_flags[NBLK];                         // per-block step flags

__device__ __forceinline__ float gelu_f(float x) {
    float x3 = x * x * x;
    float t  = tanhf(0.7978845608028654f * (x + 0.044715f * x3));
    return 0.5f * x * (1.0f + t);
}
__device__ __forceinline__ float sigm(float x) { return 1.0f / (1.0f + expf(-x)); }

__device__ __forceinline__ unsigned f2tf32(float x) {
    unsigned u;
    asm("cvt.rna.tf32.f32 %0, %1;" : "=r"(u) : "f"(x));
    return u;
}

__device__ __forceinline__ void mma_tf32(float c[4],
                                         unsigned a0, unsigned a1, unsigned a2, unsigned a3,
                                         unsigned b0, unsigned b1) {
    asm volatile(
        "mma.sync.aligned.m16n8k8.row.col.f32.tf32.tf32.f32 "
        "{%0,%1,%2,%3}, {%4,%5,%6,%7}, {%8,%9}, {%0,%1,%2,%3};\n"
        : "+f"(c[0]), "+f"(c[1]), "+f"(c[2]), "+f"(c[3])
        : "r"(a0), "r"(a1), "r"(a2), "r"(a3), "r"(b0), "r"(b1));
}

__device__ __forceinline__ void cp16(void* smem_dst, const void* gsrc) {
    unsigned d = (unsigned)__cvta_generic_to_shared(smem_dst);
    asm volatile("cp.async.ca.shared.global [%0], [%1], 16;\n" :: "r"(d), "l"(gsrc));
}
__device__ __forceinline__ void cp16cg(void* smem_dst, const void* gsrc) {
    unsigned d = (unsigned)__cvta_generic_to_shared(smem_dst);
    asm volatile("cp.async.cg.shared.global [%0], [%1], 16;\n" :: "r"(d), "l"(gsrc));
}
__device__ __forceinline__ void cp_commit() {
    asm volatile("cp.async.commit_group;\n");
}
template <int N>
__device__ __forceinline__ void cp_wait() {
    asm volatile("cp.async.wait_group %0;\n" :: "n"(N));
}

// ---------------- small utility kernels -------------------------------------
__global__ void zero_kernel(float* p, int n) {
    int i = blockIdx.x * blockDim.x + threadIdx.x;
    if (i < n) p[i] = 0.0f;
}
__global__ void zero_flags() {
    if (threadIdx.x < NBLK) g_flags[threadIdx.x] = 0u;
}

__global__ void round4_kernel(const float4* __restrict__ in,
                              float4* __restrict__ out, int n4) {
    int i = blockIdx.x * blockDim.x + threadIdx.x;
    if (i < n4) {
        float4 v = in[i];
        v.x = __uint_as_float(f2tf32(v.x));
        v.y = __uint_as_float(f2tf32(v.y));
        v.z = __uint_as_float(f2tf32(v.z));
        v.w = __uint_as_float(f2tf32(v.w));
        out[i] = v;
    }
}

// Wp[k][4j+g] = round(W[k][g*512+j])
__global__ void permute_wi(const float* __restrict__ W, float* __restrict__ Wp) {
    int idx = blockIdx.x * 256 + threadIdx.x;
    int k = idx >> 11, c = idx & 2047;
    Wp[idx] = __uint_as_float(f2tf32(W[(size_t)k * GATES_N + (c & 3) * LSTMD + (c >> 2)]));
}
__global__ void permute_wh(const float* __restrict__ W, unsigned* __restrict__ Wp) {
    int idx = blockIdx.x * 256 + threadIdx.x;
    int k = idx >> 11, c = idx & 2047;
    Wp[idx] = f2tf32(W[(size_t)k * GATES_N + (c & 3) * LSTMD + (c >> 2)]);
}
__global__ void permute_b(const float* __restrict__ b, float* __restrict__ bp) {
    int idx = blockIdx.x * 256 + threadIdx.x;
    if (idx < GATES_N) bp[idx] = b[(idx & 3) * LSTMD + (idx >> 2)];
}

// ---------------- big GEMM: C = act(A @ B + bias), cp.async double-buffered -
#define GA_STRIDE 36
#define GB_STRIDE 136
#define GA_ELEMS  (128 * GA_STRIDE)
#define GB_ELEMS  (32 * GB_STRIDE)
#define SMEM_GEMM ((2 * GA_ELEMS + 2 * GB_ELEMS) * 4)

__global__ void __launch_bounds__(256)
gemm_mma(const float* __restrict__ A,
         const float* __restrict__ B,
         const float* __restrict__ bias,
         float* __restrict__ C,
         int M, int N, int K, int do_gelu, int do_round)
{
    extern __shared__ unsigned gsm[];
    unsigned* As = gsm;
    unsigned* Bs = gsm + 2 * GA_ELEMS;

    const int bm = blockIdx.y * 128;
    const int bn = blockIdx.x * 128;
    const int tid  = threadIdx.x;
    const int warp = tid >> 5;
    const int lane = tid & 31;
    const int wm = (warp & 1) * 64;
    const int wn = (warp >> 1) * 32;
    const int r  = lane >> 2;
    const int q  = lane & 3;

    float acc[4][4][4];
#pragma unroll
    for (int mt = 0; mt < 4; mt++)
#pragma unroll
        for (int nt = 0; nt < 4; nt++)
#pragma unroll
            for (int i = 0; i < 4; i++) acc[mt][nt][i] = 0.0f;

    const float* Ab = A + (size_t)bm * K;
    const int nK = K >> 5;

    auto load_stage = [&](int kt, int buf) {
        unsigned* Ad = As + buf * GA_ELEMS;
        unsigned* Bd = Bs + buf * GB_ELEMS;
        int k0 = kt * 32;
#pragma unroll
        for (int it = 0; it < 4; it++) {
            int i  = tid + it * 256;
            int m  = i >> 3;
            int kq = (i & 7) * 4;
            cp16(&Ad[m * GA_STRIDE + kq], Ab + (size_t)m * K + k0 + kq);
        }
#pragma unroll
        for (int it = 0; it < 4; it++) {
            int i  = tid + it * 256;
            int kr = i >> 5;
            int nq = (i & 31) * 4;
            cp16(&Bd[kr * GB_STRIDE + nq], B + (size_t)(k0 + kr) * N + bn + nq);
        }
        cp_commit();
    };

    load_stage(0, 0);

    for (int kt = 0; kt < nK; kt++) {
        if (kt + 1 < nK) { load_stage(kt + 1, (kt + 1) & 1); cp_wait<1>(); }
        else             { cp_wait<0>(); }
        __syncthreads();

        const unsigned* Ac = As + (kt & 1) * GA_ELEMS;
        const unsigned* Bc = Bs + (kt & 1) * GB_ELEMS;
#pragma unroll
        for (int kk = 0; kk < 32; kk += 8) {
            unsigned af[4][4], bf[4][2];
#pragma unroll
            for (int mt = 0; mt < 4; mt++) {
                int mb = wm + mt * 16;
                af[mt][0] = Ac[(mb + r    ) * GA_STRIDE + kk + q];
                af[mt][1] = Ac[(mb + r + 8) * GA_STRIDE + kk + q];
                af[mt][2] = Ac[(mb + r    ) * GA_STRIDE + kk + q + 4];
                af[mt][3] = Ac[(mb + r + 8) * GA_STRIDE + kk + q + 4];
            }
#pragma unroll
            for (int nt = 0; nt < 4; nt++) {
                int nb = wn + nt * 8 + r;
                bf[nt][0] = Bc[(kk + q    ) * GB_STRIDE + nb];
                bf[nt][1] = Bc[(kk + q + 4) * GB_STRIDE + nb];
            }
#pragma unroll
            for (int mt = 0; mt < 4; mt++)
#pragma unroll
                for (int nt = 0; nt < 4; nt++)
                    mma_tf32(acc[mt][nt], af[mt][0], af[mt][1], af[mt][2], af[mt][3],
                             bf[nt][0], bf[nt][1]);
        }
        __syncthreads();
    }

#pragma unroll
    for (int mt = 0; mt < 4; mt++) {
#pragma unroll
        for (int nt = 0; nt < 4; nt++) {
            int row = bm + wm + mt * 16 + r;
            int col = bn + wn + nt * 8 + 2 * q;
            float b0 = bias[col], b1 = bias[col + 1];
            float z00 = acc[mt][nt][0] + b0, z01 = acc[mt][nt][1] + b1;
            float z10 = acc[mt][nt][2] + b0, z11 = acc[mt][nt][3] + b1;
            if (do_gelu) {
                z00 = gelu_f(z00); z01 = gelu_f(z01);
                z10 = gelu_f(z10); z11 = gelu_f(z11);
            }
            if (do_round) {
                z00 = __uint_as_float(f2tf32(z00));
                z01 = __uint_as_float(f2tf32(z01));
                z10 = __uint_as_float(f2tf32(z10));
                z11 = __uint_as_float(f2tf32(z11));
            }
            *reinterpret_cast<float2*>(C + (size_t)row * N + col) =
                make_float2(z00, z01);
            *reinterpret_cast<float2*>(C + (size_t)(row + 8) * N + col) =
                make_float2(z10, z11);
        }
    }
}

// ---------------- persistent fused LSTM recurrence --------------------------
// 128 blocks (32 j-tiles x 4 batch-tiles of 64 rows), weight-stationary,
// cell state in smem, h ping-pongs via g_hT.
// Barrier: per-batch-group (32 blocks sharing bt). Each block release-stores
// its flag; ONE warp polls the group's 32 flags (one 128B line).
#define WS_STRIDE 72
#define AS_STRIDE 68
#define WS_ELEMS  (LSTMD * WS_STRIDE)          /* 36864 u32 = 144KB */
#define AS_ELEMS  (64 * AS_STRIDE)             /* 4352 u32 per buf  */
#define CS_STRIDE 17
#define SMEM_LSTM ((WS_ELEMS + 2 * AS_ELEMS) * 4 + 64 * CS_STRIDE * 4)

__global__ void __launch_bounds__(256, 1)
lstm_persistent(const unsigned* __restrict__ Wp,
                const float* __restrict__ gates,
                float* __restrict__ ys)
{
    extern __shared__ unsigned smem[];
    unsigned* Ws  = smem;                          // [512][72]
    unsigned* As0 = smem + WS_ELEMS;               // [2][64][68]
    float*    Cs  = (float*)(smem + WS_ELEMS + 2 * AS_ELEMS);  // [64][17]

    const int jt = blockIdx.x;          // 0..31
    const int bt = blockIdx.y;          // 0..3
    const int bn = jt * 64;             // gate-col base
    const int bm = bt * 64;             // batch-row base
    const int tid  = threadIdx.x;
    const int warp = tid >> 5;
    const int lane = tid & 31;
    const int wm = (warp & 1) * 32;     // 2 m-warps of 32 rows
    const int wn = (warp >> 1) * 16;    // 4 n-warps of 16 cols
    const int r  = lane >> 2;
    const int q  = lane & 3;
    const int p  = q & 1;

    // load W tile (512 x 64) once; zero cell state
    for (int i = tid; i < LSTMD * 16; i += 256) {
        int k  = i >> 4;
        int nq = (i & 15) * 4;
        uint4 v = *reinterpret_cast<const uint4*>(Wp + (size_t)k * GATES_N + bn + nq);
        *reinterpret_cast<uint4*>(&Ws[k * WS_STRIDE + nq]) = v;
    }
    for (int i = tid; i < 64 * CS_STRIDE; i += 256) Cs[i] = 0.0f;
    __syncthreads();

    for (int t = 0; t < T_STEPS; t++) {
        const float* hin  = g_hT + ((t & 1) ? HT_ELEMS : 0);
        float*       hout = g_hT + ((t & 1) ? 0 : HT_ELEMS);
        const float* gx   = gates + (size_t)t * BATCH * GATES_N;

        // prefetch gx into registers (consumed only in epilogue)
        float2 gxr[2][2][2];
#pragma unroll
        for (int mt = 0; mt < 2; mt++)
#pragma unroll
            for (int nt = 0; nt < 2; nt++) {
                int row = bm + wm + mt * 16 + r;
                int col = bn + wn + nt * 8 + 2 * q;
                gxr[mt][nt][0] = *reinterpret_cast<const float2*>(
                    gx + (size_t)row * GATES_N + col);
                gxr[mt][nt][1] = *reinterpret_cast<const float2*>(
                    gx + (size_t)(row + 8) * GATES_N + col);
            }

        float acc[2][2][4];
#pragma unroll
        for (int mt = 0; mt < 2; mt++)
#pragma unroll
            for (int nt = 0; nt < 2; nt++)
#pragma unroll
                for (int i = 0; i < 4; i++) acc[mt][nt][i] = 0.0f;

        // prefetch chunk 0 (64 rows x 64 k), L2-only (h is cross-SM data)
        {
            unsigned* A = As0;
#pragma unroll
            for (int it = 0; it < 4; it++) {
                int i  = tid + it * 256;
                int m  = i >> 4;
                int kq = (i & 15) * 4;
                cp16cg(&A[m * AS_STRIDE + kq], hin + (size_t)(bm + m) * LSTMD + kq);
            }
            cp_commit();
        }

        for (int c = 0; c < 8; c++) {
            if (c < 7) {
                unsigned* A = As0 + ((c + 1) & 1) * AS_ELEMS;
                int kb = (c + 1) * 64;
#pragma unroll
                for (int it = 0; it < 4; it++) {
                    int i  = tid + it * 256;
                    int m  = i >> 4;
                    int kq = (i & 15) * 4;
                    cp16cg(&A[m * AS_STRIDE + kq],
                           hin + (size_t)(bm + m) * LSTMD + kb + kq);
                }
                cp_commit();
                cp_wait<1>();
            } else {
                cp_wait<0>();
            }
            __syncthreads();

            const unsigned* A = As0 + (c & 1) * AS_ELEMS;
            const int kbase = c * 64;
#pragma unroll
            for (int kk = 0; kk < 64; kk += 8) {
                unsigned af[2][4], bf[2][2];
#pragma unroll
                for (int mt = 0; mt < 2; mt++) {
                    int mb = wm + mt * 16;
                    af[mt][0] = A[(mb + r    ) * AS_STRIDE + kk + q];
                    af[mt][1] = A[(mb + r + 8) * AS_STRIDE + kk + q];
                    af[mt][2] = A[(mb + r    ) * AS_STRIDE + kk + q + 4];
                    af[mt][3] = A[(mb + r + 8) * AS_STRIDE + kk + q + 4];
                }
#pragma unroll
                for (int nt = 0; nt < 2; nt++) {
                    int nc = wn + nt * 8 + r;
                    bf[nt][0] = Ws[(kbase + kk + q    ) * WS_STRIDE + nc];
                    bf[nt][1] = Ws[(kbase + kk + q + 4) * WS_STRIDE + nc];
                }
#pragma unroll
                for (int mt = 0; mt < 2; mt++)
#pragma unroll
                    for (int nt = 0; nt < 2; nt++)
                        mma_tf32(acc[mt][nt], af[mt][0], af[mt][1], af[mt][2], af[mt][3],
                                 bf[nt][0], bf[nt][1]);
            }
            __syncthreads();
        }

        // epilogue: gates + cell update; write ys (fp32) + hout (tf32-rounded)
        float* yst = ys + (size_t)t * BATCH * LSTMD;
#pragma unroll
        for (int mt = 0; mt < 2; mt++) {
#pragma unroll
            for (int nt = 0; nt < 2; nt++) {
                int lrow = wm + mt * 16 + r;
                int lcol = wn + nt * 8 + 2 * q;
                float z00 = acc[mt][nt][0] + gxr[mt][nt][0].x;
                float z01 = acc[mt][nt][1] + gxr[mt][nt][0].y;
                float z10 = acc[mt][nt][2] + gxr[mt][nt][1].x;
                float z11 = acc[mt][nt][3] + gxr[mt][nt][1].y;

                float u0a = (p == 0) ? sigm(z00) : tanhf(z00);
                float u1a = sigm(z01);
                float u0b = (p == 0) ? sigm(z10) : tanhf(z10);
                float u1b = sigm(z11);

                float v0a = __shfl_xor_sync(0xffffffffu, u0a, 1);
                float v1a = __shfl_xor_sync(0xffffffffu, u1a, 1);
                float v0b = __shfl_xor_sync(0xffffffffu, u0b, 1);
                float v1b = __shfl_xor_sync(0xffffffffu, u1b, 1);

                if (p == 0) {
                    int jl = lcol >> 2;
                    int jg = jt * 16 + jl;
                    {
                        float co = Cs[lrow * CS_STRIDE + jl];
                        float cn = u1a * co + u0a * v0a;
                        Cs[lrow * CS_STRIDE + jl] = cn;
                        float h = v1a * tanhf(cn);
                        size_t gi = (size_t)(bm + lrow) * LSTMD + jg;
                        yst[gi]  = h;
                        hout[gi] = __uint_as_float(f2tf32(h));
                    }
                    {
                        int lr2 = lrow + 8;
                        float co = Cs[lr2 * CS_STRIDE + jl];
                        float cn = u1b * co + u0b * v0b;
                        Cs[lr2 * CS_STRIDE + jl] = cn;
                        float h = v1b * tanhf(cn);
                        size_t gi = (size_t)(bm + lr2) * LSTMD + jg;
                        yst[gi]  = h;
                        hout[gi] = __uint_as_float(f2tf32(h));
                    }
                }
            }
        }

        // per-batch-group barrier: 32 blocks sharing bt. h tiles for rows
        // [bm, bm+64) are produced only by blocks with the same bt, so the
        // other 96 blocks are irrelevant to this block's next step.
        if (t + 1 < T_STEPS) {
            __syncthreads();
            unsigned tgt = (unsigned)(t + 1);
            if (tid < 32) {
                if (tid == 0) {
                    __threadfence();
                    asm volatile("st.release.gpu.u32 [%0], %1;"
                                 :: "l"(&g_flags[bt * 32 + jt]), "r"(tgt) : "memory");
                }
                const unsigned* fl = &g_flags[bt * 32 + tid];
                unsigned v;
                for (;;) {
                    asm volatile("ld.acquire.gpu.u32 %0, [%1];"
                                 : "=r"(v) : "l"(fl) : "memory");
                    if (v >= tgt) break;
                }
            }
            __syncthreads();
        }
    }
}

// ---------------- heads: mu / sigma / value, one pass over ys ---------------
__global__ void heads_kernel(const float* __restrict__ Wmu,
                             const float* __restrict__ bmu,
                             const float* __restrict__ logstd,
                             const float* __restrict__ Wv,
                             const float* __restrict__ bv,
                             float* __restrict__ out)
{
    const int lane = threadIdx.x;
    const size_t row = (size_t)blockIdx.x * blockDim.y + threadIdx.y;
    const float* yrow = g_ys + row * LSTMD;

    float acc = 0.0f;
#pragma unroll 8
    for (int k = 0; k < LSTMD; k++)
        acc = fmaf(yrow[k], Wmu[k * ACTD + lane], acc);

    float* mu    = out;
    float* sigma = out + (size_t)ROWS * ACTD;
    float* value = out + (size_t)2 * ROWS * ACTD;

    mu[row * ACTD + lane]    = acc + bmu[lane];
    sigma[row * ACTD + lane] = expf(logstd[lane]);

    float v = 0.0f;
    for (int k = lane; k < LSTMD; k += 32)
        v = fmaf(yrow[k], Wv[k], v);
#pragma unroll
    for (int o = 16; o; o >>= 1) v += __shfl_xor_sync(0xffffffffu, v, o);
    if (lane == 0) value[row] = v + bv[0];
}

// ---------------- launch ----------------------------------------------------
extern "C" void kernel_launch(void* const* d_in, const int* in_sizes, int n_in,
                              void* d_out, int out_size)
{
    (void)in_sizes; (void)n_in; (void)out_size;
    const float* x      = (const float*)d_in[0];
    const float* W_enc  = (const float*)d_in[1];
    const float* b_enc  = (const float*)d_in[2];
    const float* W_i    = (const float*)d_in[3];
    const float* W_h    = (const float*)d_in[4];
    const float* b_lstm = (const float*)d_in[5];
    const float* W_mu   = (const float*)d_in[6];
    const float* b_mu   = (const float*)d_in[7];
    const float* logstd = (const float*)d_in[8];
    const float* W_v    = (const float*)d_in[9];
    const float* b_v    = (const float*)d_in[10];
    float* out = (float*)d_out;

    float *xr, *WencR, *feats, *gates, *ys, *hT, *WiP, *bP;
    unsigned* WhP;
    cudaGetSymbolAddress((void**)&xr,    g_xr);
    cudaGetSymbolAddress((void**)&WencR, g_WencR);
    cudaGetSymbolAddress((void**)&feats, g_feats);
    cudaGetSymbolAddress((void**)&gates, g_gates);
    cudaGetSymbolAddress((void**)&ys,    g_ys);
    cudaGetSymbolAddress((void**)&hT,    g_hT);
    cudaGetSymbolAddress((void**)&WiP,   g_WiP);
    cudaGetSymbolAddress((void**)&WhP,   g_WhP);
    cudaGetSymbolAddress((void**)&bP,    g_bP);

    static int attr_set = 0;
    if (!attr_set) {
        cudaFuncSetAttribute(lstm_persistent,
                             cudaFuncAttributeMaxDynamicSharedMemorySize, SMEM_LSTM);
        cudaFuncSetAttribute(gemm_mma,
                             cudaFuncAttributeMaxDynamicSharedMemorySize, SMEM_GEMM);
        attr_set = 1;
    }

    zero_kernel<<<(HT_ELEMS + 255) / 256, 256>>>(hT, HT_ELEMS);
    zero_flags<<<1, 128>>>();

    round4_kernel<<<(ROWS * OBSD / 4 + 255) / 256, 256>>>(
        (const float4*)x, (float4*)xr, ROWS * OBSD / 4);
    round4_kernel<<<(OBSD * HIDD / 4 + 255) / 256, 256>>>(
        (const float4*)W_enc, (float4*)WencR, OBSD * HIDD / 4);
    permute_wi<<<(HIDD * GATES_N) / 256, 256>>>(W_i, WiP);
    permute_wh<<<(LSTMD * GATES_N) / 256, 256>>>(W_h, WhP);
    permute_b<<<(GATES_N + 255) / 256, 256>>>(b_lstm, bP);

    {
        dim3 grid(HIDD / 128, ROWS / 128);
        gemm_mma<<<grid, 256, SMEM_GEMM>>>(xr, WencR, b_enc, feats,
                                           ROWS, HIDD, OBSD, 1, 1);
    }
    {
        dim3 grid(GATES_N / 128, ROWS / 128);
        gemm_mma<<<grid, 256, SMEM_GEMM>>>(feats, WiP, bP, gates,
                                           ROWS, GATES_N, HIDD, 0, 0);
    }
    {
        dim3 grid(32, 4);
        lstm_persistent<<<grid, 256, SMEM_LSTM>>>(WhP, gates, ys);
    }
    {
        dim3 blk(32, 8);
        heads_kernel<<<ROWS / 8, blk>>>(W_mu, b_mu, logstd, W_v, b_v, out);
    }
}

// round 8
// speedup vs baseline: 1.7578x; 1.3386x over previous
#include <cuda_runtime.h>
#include <math.h>

#define T_STEPS 512
#define BATCH   256
#define OBSD    256
#define HIDD    512
#define LSTMD   512
#define ACTD    32
#define ROWS    (T_STEPS * BATCH)   /* 131072 */
#define GATES_N (4 * LSTMD)         /* 2048 */
#define HT_ELEMS (BATCH * LSTMD)    /* 131072 */
#define NBLK     128
#define NGRP     4                  /* batch groups */
#define GRP_BLKS 32                 /* blocks per group */

// ---------------- scratch (static device globals; no runtime allocation) ----
__device__ float    g_xr   [(size_t)ROWS * OBSD];          // tf32-rounded x
__device__ float    g_WencR[(size_t)OBSD * HIDD];          // tf32-rounded W_enc
__device__ float    g_feats[(size_t)ROWS * HIDD];          // tf32-rounded feats
__device__ float    g_gates[(size_t)ROWS * GATES_N];       // permuted 4j+g
__device__ float    g_ys   [(size_t)ROWS * LSTMD];
__device__ float    g_hT   [2 * HT_ELEMS];                 // ping-pong h (tf32)
__device__ float    g_WiP  [(size_t)HIDD * GATES_N];       // permuted+rounded W_i
__device__ unsigned g_WhP  [(size_t)LSTMD * GATES_N];      // permuted W_h (tf32)
__device__ float    g_bP   [GATES_N];                      // permuted b_lstm
__device__ unsigned g_bar4 [NGRP * 32];                    // per-group counters, 128B apart

__device__ __forceinline__ float gelu_f(float x) {
    float x3 = x * x * x;
    float t  = tanhf(0.7978845608028654f * (x + 0.044715f * x3));
    return 0.5f * x * (1.0f + t);
}
__device__ __forceinline__ float sigm(float x) { return 1.0f / (1.0f + expf(-x)); }

__device__ __forceinline__ unsigned f2tf32(float x) {
    unsigned u;
    asm("cvt.rna.tf32.f32 %0, %1;" : "=r"(u) : "f"(x));
    return u;
}

__device__ __forceinline__ void mma_tf32(float c[4],
                                         unsigned a0, unsigned a1, unsigned a2, unsigned a3,
                                         unsigned b0, unsigned b1) {
    asm volatile(
        "mma.sync.aligned.m16n8k8.row.col.f32.tf32.tf32.f32 "
        "{%0,%1,%2,%3}, {%4,%5,%6,%7}, {%8,%9}, {%0,%1,%2,%3};\n"
        : "+f"(c[0]), "+f"(c[1]), "+f"(c[2]), "+f"(c[3])
        : "r"(a0), "r"(a1), "r"(a2), "r"(a3), "r"(b0), "r"(b1));
}

__device__ __forceinline__ void cp16(void* smem_dst, const void* gsrc) {
    unsigned d = (unsigned)__cvta_generic_to_shared(smem_dst);
    asm volatile("cp.async.ca.shared.global [%0], [%1], 16;\n" :: "r"(d), "l"(gsrc));
}
__device__ __forceinline__ void cp_commit() {
    asm volatile("cp.async.commit_group;\n");
}
template <int N>
__device__ __forceinline__ void cp_wait() {
    asm volatile("cp.async.wait_group %0;\n" :: "n"(N));
}

// ---------------- small utility kernels -------------------------------------
__global__ void zero_kernel(float* p, int n) {
    int i = blockIdx.x * blockDim.x + threadIdx.x;
    if (i < n) p[i] = 0.0f;
}
__global__ void zero_bar4() {
    if (threadIdx.x < NGRP * 32) g_bar4[threadIdx.x] = 0u;
}

__global__ void round4_kernel(const float4* __restrict__ in,
                              float4* __restrict__ out, int n4) {
    int i = blockIdx.x * blockDim.x + threadIdx.x;
    if (i < n4) {
        float4 v = in[i];
        v.x = __uint_as_float(f2tf32(v.x));
        v.y = __uint_as_float(f2tf32(v.y));
        v.z = __uint_as_float(f2tf32(v.z));
        v.w = __uint_as_float(f2tf32(v.w));
        out[i] = v;
    }
}

// Wp[k][4j+g] = round(W[k][g*512+j])
__global__ void permute_wi(const float* __restrict__ W, float* __restrict__ Wp) {
    int idx = blockIdx.x * 256 + threadIdx.x;
    int k = idx >> 11, c = idx & 2047;
    Wp[idx] = __uint_as_float(f2tf32(W[(size_t)k * GATES_N + (c & 3) * LSTMD + (c >> 2)]));
}
__global__ void permute_wh(const float* __restrict__ W, unsigned* __restrict__ Wp) {
    int idx = blockIdx.x * 256 + threadIdx.x;
    int k = idx >> 11, c = idx & 2047;
    Wp[idx] = f2tf32(W[(size_t)k * GATES_N + (c & 3) * LSTMD + (c >> 2)]);
}
__global__ void permute_b(const float* __restrict__ b, float* __restrict__ bp) {
    int idx = blockIdx.x * 256 + threadIdx.x;
    if (idx < GATES_N) bp[idx] = b[(idx & 3) * LSTMD + (idx >> 2)];
}

// ---------------- big GEMM: C = act(A @ B + bias), cp.async double-buffered -
#define GA_STRIDE 36
#define GB_STRIDE 136
#define GA_ELEMS  (128 * GA_STRIDE)
#define GB_ELEMS  (32 * GB_STRIDE)
#define SMEM_GEMM ((2 * GA_ELEMS + 2 * GB_ELEMS) * 4)

__global__ void __launch_bounds__(256)
gemm_mma(const float* __restrict__ A,
         const float* __restrict__ B,
         const float* __restrict__ bias,
         float* __restrict__ C,
         int M, int N, int K, int do_gelu, int do_round)
{
    extern __shared__ unsigned gsm[];
    unsigned* As = gsm;
    unsigned* Bs = gsm + 2 * GA_ELEMS;

    const int bm = blockIdx.y * 128;
    const int bn = blockIdx.x * 128;
    const int tid  = threadIdx.x;
    const int warp = tid >> 5;
    const int lane = tid & 31;
    const int wm = (warp & 1) * 64;
    const int wn = (warp >> 1) * 32;
    const int r  = lane >> 2;
    const int q  = lane & 3;

    float acc[4][4][4];
#pragma unroll
    for (int mt = 0; mt < 4; mt++)
#pragma unroll
        for (int nt = 0; nt < 4; nt++)
#pragma unroll
            for (int i = 0; i < 4; i++) acc[mt][nt][i] = 0.0f;

    const float* Ab = A + (size_t)bm * K;
    const int nK = K >> 5;

    auto load_stage = [&](int kt, int buf) {
        unsigned* Ad = As + buf * GA_ELEMS;
        unsigned* Bd = Bs + buf * GB_ELEMS;
        int k0 = kt * 32;
#pragma unroll
        for (int it = 0; it < 4; it++) {
            int i  = tid + it * 256;
            int m  = i >> 3;
            int kq = (i & 7) * 4;
            cp16(&Ad[m * GA_STRIDE + kq], Ab + (size_t)m * K + k0 + kq);
        }
#pragma unroll
        for (int it = 0; it < 4; it++) {
            int i  = tid + it * 256;
            int kr = i >> 5;
            int nq = (i & 31) * 4;
            cp16(&Bd[kr * GB_STRIDE + nq], B + (size_t)(k0 + kr) * N + bn + nq);
        }
        cp_commit();
    };

    load_stage(0, 0);

    for (int kt = 0; kt < nK; kt++) {
        if (kt + 1 < nK) { load_stage(kt + 1, (kt + 1) & 1); cp_wait<1>(); }
        else             { cp_wait<0>(); }
        __syncthreads();

        const unsigned* Ac = As + (kt & 1) * GA_ELEMS;
        const unsigned* Bc = Bs + (kt & 1) * GB_ELEMS;
#pragma unroll
        for (int kk = 0; kk < 32; kk += 8) {
            unsigned af[4][4], bf[4][2];
#pragma unroll
            for (int mt = 0; mt < 4; mt++) {
                int mb = wm + mt * 16;
                af[mt][0] = Ac[(mb + r    ) * GA_STRIDE + kk + q];
                af[mt][1] = Ac[(mb + r + 8) * GA_STRIDE + kk + q];
                af[mt][2] = Ac[(mb + r    ) * GA_STRIDE + kk + q + 4];
                af[mt][3] = Ac[(mb + r + 8) * GA_STRIDE + kk + q + 4];
            }
#pragma unroll
            for (int nt = 0; nt < 4; nt++) {
                int nb = wn + nt * 8 + r;
                bf[nt][0] = Bc[(kk + q    ) * GB_STRIDE + nb];
                bf[nt][1] = Bc[(kk + q + 4) * GB_STRIDE + nb];
            }
#pragma unroll
            for (int mt = 0; mt < 4; mt++)
#pragma unroll
                for (int nt = 0; nt < 4; nt++)
                    mma_tf32(acc[mt][nt], af[mt][0], af[mt][1], af[mt][2], af[mt][3],
                             bf[nt][0], bf[nt][1]);
        }
        __syncthreads();
    }

#pragma unroll
    for (int mt = 0; mt < 4; mt++) {
#pragma unroll
        for (int nt = 0; nt < 4; nt++) {
            int row = bm + wm + mt * 16 + r;
            int col = bn + wn + nt * 8 + 2 * q;
            float b0 = bias[col], b1 = bias[col + 1];
            float z00 = acc[mt][nt][0] + b0, z01 = acc[mt][nt][1] + b1;
            float z10 = acc[mt][nt][2] + b0, z11 = acc[mt][nt][3] + b1;
            if (do_gelu) {
                z00 = gelu_f(z00); z01 = gelu_f(z01);
                z10 = gelu_f(z10); z11 = gelu_f(z11);
            }
            if (do_round) {
                z00 = __uint_as_float(f2tf32(z00));
                z01 = __uint_as_float(f2tf32(z01));
                z10 = __uint_as_float(f2tf32(z10));
                z11 = __uint_as_float(f2tf32(z11));
            }
            *reinterpret_cast<float2*>(C + (size_t)row * N + col) =
                make_float2(z00, z01);
            *reinterpret_cast<float2*>(C + (size_t)(row + 8) * N + col) =
                make_float2(z10, z11);
        }
    }
}

// ---------------- persistent fused LSTM recurrence --------------------------
// 128 blocks (32 j-tiles x 4 batch-tiles of 64 rows), weight-stationary,
// cell state in smem, h ping-pongs via g_hT.
// Barrier: R4-style atomic counter + nanosleep poll, but ONE COUNTER PER
// BATCH GROUP (bt): only the 32 blocks sharing bt synchronize (they are the
// sole producers of the h rows this block reads next step).
#define WS_STRIDE 72
#define AS_STRIDE 68
#define WS_ELEMS  (LSTMD * WS_STRIDE)          /* 36864 u32 = 144KB */
#define AS_ELEMS  (64 * AS_STRIDE)             /* 4352 u32 per buf  */
#define CS_STRIDE 17
#define SMEM_LSTM ((WS_ELEMS + 2 * AS_ELEMS) * 4 + 64 * CS_STRIDE * 4)

__global__ void __launch_bounds__(256, 1)
lstm_persistent(const unsigned* __restrict__ Wp,
                const float* __restrict__ gates,
                float* __restrict__ ys)
{
    extern __shared__ unsigned smem[];
    unsigned* Ws  = smem;                          // [512][72]
    unsigned* As0 = smem + WS_ELEMS;               // [2][64][68]
    float*    Cs  = (float*)(smem + WS_ELEMS + 2 * AS_ELEMS);  // [64][17]

    const int jt = blockIdx.x;          // 0..31
    const int bt = blockIdx.y;          // 0..3
    const int bn = jt * 64;             // gate-col base
    const int bm = bt * 64;             // batch-row base
    const int tid  = threadIdx.x;
    const int warp = tid >> 5;
    const int lane = tid & 31;
    const int wm = (warp & 1) * 32;     // 2 m-warps of 32 rows
    const int wn = (warp >> 1) * 16;    // 4 n-warps of 16 cols
    const int r  = lane >> 2;
    const int q  = lane & 3;
    const int p  = q & 1;
    unsigned* mybar = &g_bar4[bt * 32];   // group counter (128B-separated)

    // load W tile (512 x 64) once; zero cell state
    for (int i = tid; i < LSTMD * 16; i += 256) {
        int k  = i >> 4;
        int nq = (i & 15) * 4;
        uint4 v = *reinterpret_cast<const uint4*>(Wp + (size_t)k * GATES_N + bn + nq);
        *reinterpret_cast<uint4*>(&Ws[k * WS_STRIDE + nq]) = v;
    }
    for (int i = tid; i < 64 * CS_STRIDE; i += 256) Cs[i] = 0.0f;
    __syncthreads();

    for (int t = 0; t < T_STEPS; t++) {
        const float* hin  = g_hT + ((t & 1) ? HT_ELEMS : 0);
        float*       hout = g_hT + ((t & 1) ? 0 : HT_ELEMS);
        const float* gx   = gates + (size_t)t * BATCH * GATES_N;

        // prefetch gx into registers (consumed only in epilogue)
        float2 gxr[2][2][2];
#pragma unroll
        for (int mt = 0; mt < 2; mt++)
#pragma unroll
            for (int nt = 0; nt < 2; nt++) {
                int row = bm + wm + mt * 16 + r;
                int col = bn + wn + nt * 8 + 2 * q;
                gxr[mt][nt][0] = *reinterpret_cast<const float2*>(
                    gx + (size_t)row * GATES_N + col);
                gxr[mt][nt][1] = *reinterpret_cast<const float2*>(
                    gx + (size_t)(row + 8) * GATES_N + col);
            }

        float acc[2][2][4];
#pragma unroll
        for (int mt = 0; mt < 2; mt++)
#pragma unroll
            for (int nt = 0; nt < 2; nt++)
#pragma unroll
                for (int i = 0; i < 4; i++) acc[mt][nt][i] = 0.0f;

        // prefetch chunk 0 (64 rows x 64 k)
        {
            unsigned* A = As0;
#pragma unroll
            for (int it = 0; it < 4; it++) {
                int i  = tid + it * 256;
                int m  = i >> 4;
                int kq = (i & 15) * 4;
                cp16(&A[m * AS_STRIDE + kq], hin + (size_t)(bm + m) * LSTMD + kq);
            }
            cp_commit();
        }

        for (int c = 0; c < 8; c++) {
            if (c < 7) {
                unsigned* A = As0 + ((c + 1) & 1) * AS_ELEMS;
                int kb = (c + 1) * 64;
#pragma unroll
                for (int it = 0; it < 4; it++) {
                    int i  = tid + it * 256;
                    int m  = i >> 4;
                    int kq = (i & 15) * 4;
                    cp16(&A[m * AS_STRIDE + kq],
                         hin + (size_t)(bm + m) * LSTMD + kb + kq);
                }
                cp_commit();
                cp_wait<1>();
            } else {
                cp_wait<0>();
            }
            __syncthreads();

            const unsigned* A = As0 + (c & 1) * AS_ELEMS;
            const int kbase = c * 64;
#pragma unroll
            for (int kk = 0; kk < 64; kk += 8) {
                unsigned af[2][4], bf[2][2];
#pragma unroll
                for (int mt = 0; mt < 2; mt++) {
                    int mb = wm + mt * 16;
                    af[mt][0] = A[(mb + r    ) * AS_STRIDE + kk + q];
                    af[mt][1] = A[(mb + r + 8) * AS_STRIDE + kk + q];
                    af[mt][2] = A[(mb + r    ) * AS_STRIDE + kk + q + 4];
                    af[mt][3] = A[(mb + r + 8) * AS_STRIDE + kk + q + 4];
                }
#pragma unroll
                for (int nt = 0; nt < 2; nt++) {
                    int nc = wn + nt * 8 + r;
                    bf[nt][0] = Ws[(kbase + kk + q    ) * WS_STRIDE + nc];
                    bf[nt][1] = Ws[(kbase + kk + q + 4) * WS_STRIDE + nc];
                }
#pragma unroll
                for (int mt = 0; mt < 2; mt++)
#pragma unroll
                    for (int nt = 0; nt < 2; nt++)
                        mma_tf32(acc[mt][nt], af[mt][0], af[mt][1], af[mt][2], af[mt][3],
                                 bf[nt][0], bf[nt][1]);
            }
            __syncthreads();
        }

        // epilogue: gates + cell update; write ys (fp32) + hout (tf32-rounded)
        float* yst = ys + (size_t)t * BATCH * LSTMD;
#pragma unroll
        for (int mt = 0; mt < 2; mt++) {
#pragma unroll
            for (int nt = 0; nt < 2; nt++) {
                int lrow = wm + mt * 16 + r;
                int lcol = wn + nt * 8 + 2 * q;
                float z00 = acc[mt][nt][0] + gxr[mt][nt][0].x;
                float z01 = acc[mt][nt][1] + gxr[mt][nt][0].y;
                float z10 = acc[mt][nt][2] + gxr[mt][nt][1].x;
                float z11 = acc[mt][nt][3] + gxr[mt][nt][1].y;

                float u0a = (p == 0) ? sigm(z00) : tanhf(z00);
                float u1a = sigm(z01);
                float u0b = (p == 0) ? sigm(z10) : tanhf(z10);
                float u1b = sigm(z11);

                float v0a = __shfl_xor_sync(0xffffffffu, u0a, 1);
                float v1a = __shfl_xor_sync(0xffffffffu, u1a, 1);
                float v0b = __shfl_xor_sync(0xffffffffu, u0b, 1);
                float v1b = __shfl_xor_sync(0xffffffffu, u1b, 1);

                if (p == 0) {
                    int jl = lcol >> 2;
                    int jg = jt * 16 + jl;
                    {
                        float co = Cs[lrow * CS_STRIDE + jl];
                        float cn = u1a * co + u0a * v0a;
                        Cs[lrow * CS_STRIDE + jl] = cn;
                        float h = v1a * tanhf(cn);
                        size_t gi = (size_t)(bm + lrow) * LSTMD + jg;
                        yst[gi]  = h;
                        hout[gi] = __uint_as_float(f2tf32(h));
                    }
                    {
                        int lr2 = lrow + 8;
                        float co = Cs[lr2 * CS_STRIDE + jl];
                        float cn = u1b * co + u0b * v0b;
                        Cs[lr2 * CS_STRIDE + jl] = cn;
                        float h = v1b * tanhf(cn);
                        size_t gi = (size_t)(bm + lr2) * LSTMD + jg;
                        yst[gi]  = h;
                        hout[gi] = __uint_as_float(f2tf32(h));
                    }
                }
            }
        }

        // per-batch-group barrier (R4 mechanics, group-local counter)
        if (t + 1 < T_STEPS) {
            __syncthreads();
            if (tid == 0) {
                __threadfence();
                atomicAdd(mybar, 1u);
                unsigned tgt = (unsigned)(t + 1) * GRP_BLKS;
                unsigned v;
                for (;;) {
                    asm volatile("ld.acquire.gpu.u32 %0, [%1];"
                                 : "=r"(v) : "l"(mybar) : "memory");
                    if (v >= tgt) break;
                    __nanosleep(32);
                }
            }
            __syncthreads();
        }
    }
}

// ---------------- heads: mu / sigma / value, one pass over ys ---------------
__global__ void heads_kernel(const float* __restrict__ Wmu,
                             const float* __restrict__ bmu,
                             const float* __restrict__ logstd,
                             const float* __restrict__ Wv,
                             const float* __restrict__ bv,
                             float* __restrict__ out)
{
    const int lane = threadIdx.x;
    const size_t row = (size_t)blockIdx.x * blockDim.y + threadIdx.y;
    const float* yrow = g_ys + row * LSTMD;

    float acc = 0.0f;
#pragma unroll 8
    for (int k = 0; k < LSTMD; k++)
        acc = fmaf(yrow[k], Wmu[k * ACTD + lane], acc);

    float* mu    = out;
    float* sigma = out + (size_t)ROWS * ACTD;
    float* value = out + (size_t)2 * ROWS * ACTD;

    mu[row * ACTD + lane]    = acc + bmu[lane];
    sigma[row * ACTD + lane] = expf(logstd[lane]);

    float v = 0.0f;
    for (int k = lane; k < LSTMD; k += 32)
        v = fmaf(yrow[k], Wv[k], v);
#pragma unroll
    for (int o = 16; o; o >>= 1) v += __shfl_xor_sync(0xffffffffu, v, o);
    if (lane == 0) value[row] = v + bv[0];
}

// ---------------- launch ----------------------------------------------------
extern "C" void kernel_launch(void* const* d_in, const int* in_sizes, int n_in,
                              void* d_out, int out_size)
{
    (void)in_sizes; (void)n_in; (void)out_size;
    const float* x      = (const float*)d_in[0];
    const float* W_enc  = (const float*)d_in[1];
    const float* b_enc  = (const float*)d_in[2];
    const float* W_i    = (const float*)d_in[3];
    const float* W_h    = (const float*)d_in[4];
    const float* b_lstm = (const float*)d_in[5];
    const float* W_mu   = (const float*)d_in[6];
    const float* b_mu   = (const float*)d_in[7];
    const float* logstd = (const float*)d_in[8];
    const float* W_v    = (const float*)d_in[9];
    const float* b_v    = (const float*)d_in[10];
    float* out = (float*)d_out;

    float *xr, *WencR, *feats, *gates, *ys, *hT, *WiP, *bP;
    unsigned* WhP;
    cudaGetSymbolAddress((void**)&xr,    g_xr);
    cudaGetSymbolAddress((void**)&WencR, g_WencR);
    cudaGetSymbolAddress((void**)&feats, g_feats);
    cudaGetSymbolAddress((void**)&gates, g_gates);
    cudaGetSymbolAddress((void**)&ys,    g_ys);
    cudaGetSymbolAddress((void**)&hT,    g_hT);
    cudaGetSymbolAddress((void**)&WiP,   g_WiP);
    cudaGetSymbolAddress((void**)&WhP,   g_WhP);
    cudaGetSymbolAddress((void**)&bP,    g_bP);

    static int attr_set = 0;
    if (!attr_set) {
        cudaFuncSetAttribute(lstm_persistent,
                             cudaFuncAttributeMaxDynamicSharedMemorySize, SMEM_LSTM);
        cudaFuncSetAttribute(gemm_mma,
                             cudaFuncAttributeMaxDynamicSharedMemorySize, SMEM_GEMM);
        attr_set = 1;
    }

    zero_kernel<<<(HT_ELEMS + 255) / 256, 256>>>(hT, HT_ELEMS);
    zero_bar4<<<1, 128>>>();

    round4_kernel<<<(ROWS * OBSD / 4 + 255) / 256, 256>>>(
        (const float4*)x, (float4*)xr, ROWS * OBSD / 4);
    round4_kernel<<<(OBSD * HIDD / 4 + 255) / 256, 256>>>(
        (const float4*)W_enc, (float4*)WencR, OBSD * HIDD / 4);
    permute_wi<<<(HIDD * GATES_N) / 256, 256>>>(W_i, WiP);
    permute_wh<<<(LSTMD * GATES_N) / 256, 256>>>(W_h, WhP);
    permute_b<<<(GATES_N + 255) / 256, 256>>>(b_lstm, bP);

    {
        dim3 grid(HIDD / 128, ROWS / 128);
        gemm_mma<<<grid, 256, SMEM_GEMM>>>(xr, WencR, b_enc, feats,
                                           ROWS, HIDD, OBSD, 1, 1);
    }
    {
        dim3 grid(GATES_N / 128, ROWS / 128);
        gemm_mma<<<grid, 256, SMEM_GEMM>>>(feats, WiP, bP, gates,
                                           ROWS, GATES_N, HIDD, 0, 0);
    }
    {
        dim3 grid(32, 4);
        lstm_persistent<<<grid, 256, SMEM_LSTM>>>(WhP, gates, ys);
    }
    {
        dim3 blk(32, 8);
        heads_kernel<<<ROWS / 8, blk>>>(W_mu, b_mu, logstd, W_v, b_v, out);
    }
}

// round 12
// speedup vs baseline: 1.9070x; 1.0849x over previous
#include <cuda_runtime.h>
#include <math.h>
#include <stdint.h>

#define T_STEPS 512
#define BATCH   256
#define OBSD    256
#define HIDD    512
#define LSTMD   512
#define ACTD    32
#define ROWS    (T_STEPS * BATCH)   /* 131072 */
#define GATES_N (4 * LSTMD)         /* 2048 */
#define HT_ELEMS (BATCH * LSTMD)    /* 131072 */
#define NGRP     4
#define GRP_BLKS 32

// one extern-shared symbol for all dynamic-smem kernels
extern __shared__ char dynsmem[];

// ---------------- scratch (static device globals) ---------------------------
__device__ float    g_xr   [(size_t)ROWS * OBSD];
__device__ float    g_WencR[(size_t)OBSD * HIDD];
__device__ float    g_feats[(size_t)ROWS * HIDD];
__device__ float    g_gates[(size_t)ROWS * GATES_N];
__device__ float    g_ys   [(size_t)ROWS * LSTMD];
__device__ float    g_hT   [2 * HT_ELEMS];
__device__ float    g_WiP  [(size_t)HIDD * GATES_N];
__device__ unsigned g_WhP  [(size_t)LSTMD * GATES_N];
__device__ float    g_bP   [GATES_N];
__device__ float    g_Whd  [(size_t)LSTMD * 64];     // heads weights [k][64]
__device__ unsigned g_bar4 [NGRP * 32];

__device__ __forceinline__ float gelu_f(float x) {
    float x3 = x * x * x;
    float t  = tanhf(0.7978845608028654f * (x + 0.044715f * x3));
    return 0.5f * x * (1.0f + t);
}
__device__ __forceinline__ float sigm(float x) { return 1.0f / (1.0f + expf(-x)); }

__device__ __forceinline__ unsigned f2tf32(float x) {
    unsigned u;
    asm("cvt.rna.tf32.f32 %0, %1;" : "=r"(u) : "f"(x));
    return u;
}

__device__ __forceinline__ void mma_tf32(float c[4],
                                         unsigned a0, unsigned a1, unsigned a2, unsigned a3,
                                         unsigned b0, unsigned b1) {
    asm volatile(
        "mma.sync.aligned.m16n8k8.row.col.f32.tf32.tf32.f32 "
        "{%0,%1,%2,%3}, {%4,%5,%6,%7}, {%8,%9}, {%0,%1,%2,%3};\n"
        : "+f"(c[0]), "+f"(c[1]), "+f"(c[2]), "+f"(c[3])
        : "r"(a0), "r"(a1), "r"(a2), "r"(a3), "r"(b0), "r"(b1));
}

__device__ __forceinline__ void ldsm4(unsigned f[4], uint32_t addr) {
    asm volatile("ldmatrix.sync.aligned.m8n8.x4.shared.b16 {%0,%1,%2,%3}, [%4];"
                 : "=r"(f[0]), "=r"(f[1]), "=r"(f[2]), "=r"(f[3]) : "r"(addr));
}

__device__ __forceinline__ void cp16(void* smem_dst, const void* gsrc) {
    unsigned d = (unsigned)__cvta_generic_to_shared(smem_dst);
    asm volatile("cp.async.ca.shared.global [%0], [%1], 16;\n" :: "r"(d), "l"(gsrc));
}
__device__ __forceinline__ void cp_commit() {
    asm volatile("cp.async.commit_group;\n");
}
template <int N>
__device__ __forceinline__ void cp_wait() {
    asm volatile("cp.async.wait_group %0;\n" :: "n"(N));
}

// ---------------- small utility kernels -------------------------------------
__global__ void zero_kernel(float* p, int n) {
    int i = blockIdx.x * blockDim.x + threadIdx.x;
    if (i < n) p[i] = 0.0f;
}
__global__ void zero_bar4() {
    if (threadIdx.x < NGRP * 32) g_bar4[threadIdx.x] = 0u;
}

__global__ void round4_kernel(const float4* __restrict__ in,
                              float4* __restrict__ out, int n4) {
    int i = blockIdx.x * blockDim.x + threadIdx.x;
    if (i < n4) {
        float4 v = in[i];
        v.x = __uint_as_float(f2tf32(v.x));
        v.y = __uint_as_float(f2tf32(v.y));
        v.z = __uint_as_float(f2tf32(v.z));
        v.w = __uint_as_float(f2tf32(v.w));
        out[i] = v;
    }
}

__global__ void permute_wi(const float* __restrict__ W, float* __restrict__ Wp) {
    int idx = blockIdx.x * 256 + threadIdx.x;
    int k = idx >> 11, c = idx & 2047;
    Wp[idx] = __uint_as_float(f2tf32(W[(size_t)k * GATES_N + (c & 3) * LSTMD + (c >> 2)]));
}
__global__ void permute_wh(const float* __restrict__ W, unsigned* __restrict__ Wp) {
    int idx = blockIdx.x * 256 + threadIdx.x;
    int k = idx >> 11, c = idx & 2047;
    Wp[idx] = f2tf32(W[(size_t)k * GATES_N + (c & 3) * LSTMD + (c >> 2)]);
}
__global__ void permute_b(const float* __restrict__ b, float* __restrict__ bp) {
    int idx = blockIdx.x * 256 + threadIdx.x;
    if (idx < GATES_N) bp[idx] = b[(idx & 3) * LSTMD + (idx >> 2)];
}
// Whd[k][n]: n<32 -> W_mu[k][n]; n==32 -> W_v[k]; else 0   (tf32-rounded)
__global__ void prep_whd(const float* __restrict__ Wmu,
                         const float* __restrict__ Wv,
                         float* __restrict__ Whd) {
    int idx = blockIdx.x * 256 + threadIdx.x;     // < 512*64
    int k = idx >> 6, n = idx & 63;
    float v = 0.0f;
    if (n < 32)       v = Wmu[k * ACTD + n];
    else if (n == 32) v = Wv[k];
    Whd[idx] = __uint_as_float(f2tf32(v));
}

// ---------------- big GEMM (R8, unchanged): cp.async double-buffered --------
#define GA_STRIDE 36
#define GB_STRIDE 136
#define GA_ELEMS  (128 * GA_STRIDE)
#define GB_ELEMS  (32 * GB_STRIDE)
#define SMEM_GEMM ((2 * GA_ELEMS + 2 * GB_ELEMS) * 4)

__global__ void __launch_bounds__(256)
gemm_mma(const float* __restrict__ A,
         const float* __restrict__ B,
         const float* __restrict__ bias,
         float* __restrict__ C,
         int M, int N, int K, int do_gelu, int do_round)
{
    unsigned* gsm = (unsigned*)dynsmem;
    unsigned* As = gsm;
    unsigned* Bs = gsm + 2 * GA_ELEMS;

    const int bm = blockIdx.y * 128;
    const int bn = blockIdx.x * 128;
    const int tid  = threadIdx.x;
    const int warp = tid >> 5;
    const int lane = tid & 31;
    const int wm = (warp & 1) * 64;
    const int wn = (warp >> 1) * 32;
    const int r  = lane >> 2;
    const int q  = lane & 3;

    float acc[4][4][4];
#pragma unroll
    for (int mt = 0; mt < 4; mt++)
#pragma unroll
        for (int nt = 0; nt < 4; nt++)
#pragma unroll
            for (int i = 0; i < 4; i++) acc[mt][nt][i] = 0.0f;

    const float* Ab = A + (size_t)bm * K;
    const int nK = K >> 5;

    auto load_stage = [&](int kt, int buf) {
        unsigned* Ad = As + buf * GA_ELEMS;
        unsigned* Bd = Bs + buf * GB_ELEMS;
        int k0 = kt * 32;
#pragma unroll
        for (int it = 0; it < 4; it++) {
            int i  = tid + it * 256;
            int m  = i >> 3;
            int kq = (i & 7) * 4;
            cp16(&Ad[m * GA_STRIDE + kq], Ab + (size_t)m * K + k0 + kq);
        }
#pragma unroll
        for (int it = 0; it < 4; it++) {
            int i  = tid + it * 256;
            int kr = i >> 5;
            int nq = (i & 31) * 4;
            cp16(&Bd[kr * GB_STRIDE + nq], B + (size_t)(k0 + kr) * N + bn + nq);
        }
        cp_commit();
    };

    load_stage(0, 0);

    for (int kt = 0; kt < nK; kt++) {
        if (kt + 1 < nK) { load_stage(kt + 1, (kt + 1) & 1); cp_wait<1>(); }
        else             { cp_wait<0>(); }
        __syncthreads();

        const unsigned* Ac = As + (kt & 1) * GA_ELEMS;
        const unsigned* Bc = Bs + (kt & 1) * GB_ELEMS;
#pragma unroll
        for (int kk = 0; kk < 32; kk += 8) {
            unsigned af[4][4], bf[4][2];
#pragma unroll
            for (int mt = 0; mt < 4; mt++) {
                int mb = wm + mt * 16;
                af[mt][0] = Ac[(mb + r    ) * GA_STRIDE + kk + q];
                af[mt][1] = Ac[(mb + r + 8) * GA_STRIDE + kk + q];
                af[mt][2] = Ac[(mb + r    ) * GA_STRIDE + kk + q + 4];
                af[mt][3] = Ac[(mb + r + 8) * GA_STRIDE + kk + q + 4];
            }
#pragma unroll
            for (int nt = 0; nt < 4; nt++) {
                int nb = wn + nt * 8 + r;
                bf[nt][0] = Bc[(kk + q    ) * GB_STRIDE + nb];
                bf[nt][1] = Bc[(kk + q + 4) * GB_STRIDE + nb];
            }
#pragma unroll
            for (int mt = 0; mt < 4; mt++)
#pragma unroll
                for (int nt = 0; nt < 4; nt++)
                    mma_tf32(acc[mt][nt], af[mt][0], af[mt][1], af[mt][2], af[mt][3],
                             bf[nt][0], bf[nt][1]);
        }
        __syncthreads();
    }

#pragma unroll
    for (int mt = 0; mt < 4; mt++) {
#pragma unroll
        for (int nt = 0; nt < 4; nt++) {
            int row = bm + wm + mt * 16 + r;
            int col = bn + wn + nt * 8 + 2 * q;
            float b0 = bias[col], b1 = bias[col + 1];
            float z00 = acc[mt][nt][0] + b0, z01 = acc[mt][nt][1] + b1;
            float z10 = acc[mt][nt][2] + b0, z11 = acc[mt][nt][3] + b1;
            if (do_gelu) {
                z00 = gelu_f(z00); z01 = gelu_f(z01);
                z10 = gelu_f(z10); z11 = gelu_f(z11);
            }
            if (do_round) {
                z00 = __uint_as_float(f2tf32(z00));
                z01 = __uint_as_float(f2tf32(z01));
                z10 = __uint_as_float(f2tf32(z10));
                z11 = __uint_as_float(f2tf32(z11));
            }
            *reinterpret_cast<float2*>(C + (size_t)row * N + col) =
                make_float2(z00, z01);
            *reinterpret_cast<float2*>(C + (size_t)(row + 8) * N + col) =
                make_float2(z10, z11);
        }
    }
}

// ---------------- persistent fused LSTM recurrence (ldmatrix k-loop) --------
// 128 blocks (32 j x 4 b), W_h transposed in smem [n][k] (ldmatrix B frags),
// h tile [m][k] (ldmatrix A frags), per-batch-group barrier (R7).
#define WT_STRIDE 516                           /* 512 + 4; 2064B = 129*16 */
#define WT_ELEMS  (64 * WT_STRIDE)              /* 33024 u32 */
#define AS_STRIDE 68                            /* 272B = 17*16 */
#define AS_ELEMS  (64 * AS_STRIDE)              /* 4352 u32 */
#define CS_STRIDE 17
#define SMEM_LSTM ((WT_ELEMS + 2 * AS_ELEMS + 64 * CS_STRIDE) * 4)

__global__ void __launch_bounds__(256, 1)
lstm_persistent(const unsigned* __restrict__ Wp,
                const float* __restrict__ gates,
                float* __restrict__ ys)
{
    unsigned* smem = (unsigned*)dynsmem;
    unsigned* Wst = smem;                               // [64][516]  (n, k)
    unsigned* As0 = smem + WT_ELEMS;                    // [2][64][68] (m, k)
    float*    Cs  = (float*)(smem + WT_ELEMS + 2 * AS_ELEMS);  // [64][17]

    const int jt = blockIdx.x;
    const int bt = blockIdx.y;
    const int bn = jt * 64;
    const int bm = bt * 64;
    const int tid  = threadIdx.x;
    const int warp = tid >> 5;
    const int lane = tid & 31;
    const int wm = (warp & 1) * 32;
    const int wn = (warp >> 1) * 16;
    const int r  = lane >> 2;
    const int q  = lane & 3;
    const int p  = q & 1;
    unsigned* mybar = &g_bar4[bt * 32];

    // W tile transposed into smem once: Wst[n][k] = Wp[k][bn+n]
    for (int i = tid; i < 64 * LSTMD; i += 256) {
        int n = i & 63, k = i >> 6;
        Wst[n * WT_STRIDE + k] = Wp[(size_t)k * GATES_N + bn + n];
    }
    for (int i = tid; i < 64 * CS_STRIDE; i += 256) Cs[i] = 0.0f;
    __syncthreads();

    // ldmatrix lane-address precompute (byte addresses in shared space)
    const uint32_t smem_u32 = (uint32_t)__cvta_generic_to_shared(dynsmem);
    const uint32_t as_base  = smem_u32 + WT_ELEMS * 4;
    uint32_t a_rel[2];
#pragma unroll
    for (int mt = 0; mt < 2; mt++)
        a_rel[mt] = (uint32_t)(((wm + mt * 16 + (lane & 15)) * AS_STRIDE
                                + ((lane >> 4) << 2)) * 4);
    const uint32_t b_base = smem_u32 +
        (uint32_t)((((wn + ((lane >> 4) << 3) + (lane & 7)) * WT_STRIDE)
                    + (((lane >> 3) & 1) << 2)) * 4);

    for (int t = 0; t < T_STEPS; t++) {
        const float* hin  = g_hT + ((t & 1) ? HT_ELEMS : 0);
        float*       hout = g_hT + ((t & 1) ? 0 : HT_ELEMS);
        const float* gx   = gates + (size_t)t * BATCH * GATES_N;

        float2 gxr[2][2][2];
#pragma unroll
        for (int mt = 0; mt < 2; mt++)
#pragma unroll
            for (int nt = 0; nt < 2; nt++) {
                int row = bm + wm + mt * 16 + r;
                int col = bn + wn + nt * 8 + 2 * q;
                gxr[mt][nt][0] = *reinterpret_cast<const float2*>(
                    gx + (size_t)row * GATES_N + col);
                gxr[mt][nt][1] = *reinterpret_cast<const float2*>(
                    gx + (size_t)(row + 8) * GATES_N + col);
            }

        float acc[2][2][4];
#pragma unroll
        for (int mt = 0; mt < 2; mt++)
#pragma unroll
            for (int nt = 0; nt < 2; nt++)
#pragma unroll
                for (int i = 0; i < 4; i++) acc[mt][nt][i] = 0.0f;

        {
            unsigned* A = As0;
#pragma unroll
            for (int it = 0; it < 4; it++) {
                int i  = tid + it * 256;
                int m  = i >> 4;
                int kq = (i & 15) * 4;
                cp16(&A[m * AS_STRIDE + kq], hin + (size_t)(bm + m) * LSTMD + kq);
            }
            cp_commit();
        }

        for (int c = 0; c < 8; c++) {
            if (c < 7) {
                unsigned* A = As0 + ((c + 1) & 1) * AS_ELEMS;
                int kb = (c + 1) * 64;
#pragma unroll
                for (int it = 0; it < 4; it++) {
                    int i  = tid + it * 256;
                    int m  = i >> 4;
                    int kq = (i & 15) * 4;
                    cp16(&A[m * AS_STRIDE + kq],
                         hin + (size_t)(bm + m) * LSTMD + kb + kq);
                }
                cp_commit();
                cp_wait<1>();
            } else {
                cp_wait<0>();
            }
            __syncthreads();

            const uint32_t abuf  = as_base + (uint32_t)((c & 1) * AS_ELEMS * 4);
            const int      kbase = c * 64;
#pragma unroll
            for (int kk = 0; kk < 64; kk += 8) {
                unsigned af0[4], af1[4], bf[4];
                ldsm4(af0, abuf + a_rel[0] + kk * 4);
                ldsm4(af1, abuf + a_rel[1] + kk * 4);
                ldsm4(bf,  b_base + (uint32_t)((kbase + kk) * 4));
                mma_tf32(acc[0][0], af0[0], af0[1], af0[2], af0[3], bf[0], bf[1]);
                mma_tf32(acc[0][1], af0[0], af0[1], af0[2], af0[3], bf[2], bf[3]);
                mma_tf32(acc[1][0], af1[0], af1[1], af1[2], af1[3], bf[0], bf[1]);
                mma_tf32(acc[1][1], af1[0], af1[1], af1[2], af1[3], bf[2], bf[3]);
            }
            __syncthreads();
        }

        float* yst = ys + (size_t)t * BATCH * LSTMD;
#pragma unroll
        for (int mt = 0; mt < 2; mt++) {
#pragma unroll
            for (int nt = 0; nt < 2; nt++) {
                int lrow = wm + mt * 16 + r;
                int lcol = wn + nt * 8 + 2 * q;
                float z00 = acc[mt][nt][0] + gxr[mt][nt][0].x;
                float z01 = acc[mt][nt][1] + gxr[mt][nt][0].y;
                float z10 = acc[mt][nt][2] + gxr[mt][nt][1].x;
                float z11 = acc[mt][nt][3] + gxr[mt][nt][1].y;

                float u0a = (p == 0) ? sigm(z00) : tanhf(z00);
                float u1a = sigm(z01);
                float u0b = (p == 0) ? sigm(z10) : tanhf(z10);
                float u1b = sigm(z11);

                float v0a = __shfl_xor_sync(0xffffffffu, u0a, 1);
                float v1a = __shfl_xor_sync(0xffffffffu, u1a, 1);
                float v0b = __shfl_xor_sync(0xffffffffu, u0b, 1);
                float v1b = __shfl_xor_sync(0xffffffffu, u1b, 1);

                if (p == 0) {
                    int jl = lcol >> 2;
                    int jg = jt * 16 + jl;
                    {
                        float co = Cs[lrow * CS_STRIDE + jl];
                        float cn = u1a * co + u0a * v0a;
                        Cs[lrow * CS_STRIDE + jl] = cn;
                        float h = v1a * tanhf(cn);
                        size_t gi = (size_t)(bm + lrow) * LSTMD + jg;
                        yst[gi]  = h;
                        hout[gi] = __uint_as_float(f2tf32(h));
                    }
                    {
                        int lr2 = lrow + 8;
                        float co = Cs[lr2 * CS_STRIDE + jl];
                        float cn = u1b * co + u0b * v0b;
                        Cs[lr2 * CS_STRIDE + jl] = cn;
                        float h = v1b * tanhf(cn);
                        size_t gi = (size_t)(bm + lr2) * LSTMD + jg;
                        yst[gi]  = h;
                        hout[gi] = __uint_as_float(f2tf32(h));
                    }
                }
            }
        }

        if (t + 1 < T_STEPS) {
            __syncthreads();
            if (tid == 0) {
                __threadfence();
                atomicAdd(mybar, 1u);
                unsigned tgt = (unsigned)(t + 1) * GRP_BLKS;
                unsigned v;
                for (;;) {
                    asm volatile("ld.acquire.gpu.u32 %0, [%1];"
                                 : "=r"(v) : "l"(mybar) : "memory");
                    if (v >= tgt) break;
                    __nanosleep(32);
                }
            }
            __syncthreads();
        }
    }
}

// ---------------- heads as tf32 mma GEMM: [mu|value] = ys @ Whd -------------
// BM=128, BN=64, K=512; static smem, synchronous cvt loader.
__global__ void __launch_bounds__(256)
heads_mma(const float* __restrict__ Whd,    // [512][64] tf32-rounded
          const float* __restrict__ bmu,
          const float* __restrict__ logstd,
          const float* __restrict__ bv,
          float* __restrict__ out)
{
    __shared__ unsigned As[128][36];
    __shared__ unsigned Bs[32][72];

    const int bm = blockIdx.x * 128;
    const int tid  = threadIdx.x;
    const int warp = tid >> 5;
    const int lane = tid & 31;
    const int wm = (warp & 1) * 64;
    const int wn = (warp >> 1) * 16;
    const int r  = lane >> 2;
    const int q  = lane & 3;

    float acc[4][2][4];
#pragma unroll
    for (int mt = 0; mt < 4; mt++)
#pragma unroll
        for (int nt = 0; nt < 2; nt++)
#pragma unroll
            for (int i = 0; i < 4; i++) acc[mt][nt][i] = 0.0f;

    const float* Ab = g_ys + (size_t)bm * LSTMD;

    for (int k0 = 0; k0 < LSTMD; k0 += 32) {
#pragma unroll
        for (int it = 0; it < 4; it++) {             // A 128x32, cvt to tf32
            int i  = tid + it * 256;
            int m  = i >> 3;
            int kq = (i & 7) * 4;
            float4 v = *reinterpret_cast<const float4*>(
                Ab + (size_t)m * LSTMD + k0 + kq);
            unsigned* d = &As[m][kq];
            d[0] = f2tf32(v.x); d[1] = f2tf32(v.y);
            d[2] = f2tf32(v.z); d[3] = f2tf32(v.w);
        }
#pragma unroll
        for (int it = 0; it < 2; it++) {             // B 32x64 (already rounded)
            int i  = tid + it * 256;
            int kr = i >> 4;
            int nq = (i & 15) * 4;
            uint4 v = *reinterpret_cast<const uint4*>(
                Whd + (size_t)(k0 + kr) * 64 + nq);
            *reinterpret_cast<uint4*>(&Bs[kr][nq]) = v;
        }
        __syncthreads();

#pragma unroll
        for (int kk = 0; kk < 32; kk += 8) {
            unsigned af[4][4], bf[2][2];
#pragma unroll
            for (int mt = 0; mt < 4; mt++) {
                int mb = wm + mt * 16;
                af[mt][0] = As[mb + r    ][kk + q];
                af[mt][1] = As[mb + r + 8][kk + q];
                af[mt][2] = As[mb + r    ][kk + q + 4];
                af[mt][3] = As[mb + r + 8][kk + q + 4];
            }
#pragma unroll
            for (int nt = 0; nt < 2; nt++) {
                int nb = wn + nt * 8 + r;
                bf[nt][0] = Bs[kk + q    ][nb];
                bf[nt][1] = Bs[kk + q + 4][nb];
            }
#pragma unroll
            for (int mt = 0; mt < 4; mt++)
#pragma unroll
                for (int nt = 0; nt < 2; nt++)
                    mma_tf32(acc[mt][nt], af[mt][0], af[mt][1], af[mt][2], af[mt][3],
                             bf[nt][0], bf[nt][1]);
        }
        __syncthreads();
    }

    float* mu    = out;
    float* sigma = out + (size_t)ROWS * ACTD;
    float* value = out + (size_t)2 * ROWS * ACTD;

#pragma unroll
    for (int mt = 0; mt < 4; mt++) {
#pragma unroll
        for (int nt = 0; nt < 2; nt++) {
            int row = bm + wm + mt * 16 + r;
            int col = wn + nt * 8 + 2 * q;
            if (col < 32) {
                float b0 = bmu[col], b1 = bmu[col + 1];
                float s0 = expf(logstd[col]), s1 = expf(logstd[col + 1]);
                mu[(size_t)row * ACTD + col]           = acc[mt][nt][0] + b0;
                mu[(size_t)row * ACTD + col + 1]       = acc[mt][nt][1] + b1;
                mu[(size_t)(row + 8) * ACTD + col]     = acc[mt][nt][2] + b0;
                mu[(size_t)(row + 8) * ACTD + col + 1] = acc[mt][nt][3] + b1;
                sigma[(size_t)row * ACTD + col]           = s0;
                sigma[(size_t)row * ACTD + col + 1]       = s1;
                sigma[(size_t)(row + 8) * ACTD + col]     = s0;
                sigma[(size_t)(row + 8) * ACTD + col + 1] = s1;
            } else if (col == 32) {
                value[row]     = acc[mt][nt][0] + bv[0];
                value[row + 8] = acc[mt][nt][2] + bv[0];
            }
        }
    }
}

// ---------------- launch ----------------------------------------------------
extern "C" void kernel_launch(void* const* d_in, const int* in_sizes, int n_in,
                              void* d_out, int out_size)
{
    (void)in_sizes; (void)n_in; (void)out_size;
    const float* x      = (const float*)d_in[0];
    const float* W_enc  = (const float*)d_in[1];
    const float* b_enc  = (const float*)d_in[2];
    const float* W_i    = (const float*)d_in[3];
    const float* W_h    = (const float*)d_in[4];
    const float* b_lstm = (const float*)d_in[5];
    const float* W_mu   = (const float*)d_in[6];
    const float* b_mu   = (const float*)d_in[7];
    const float* logstd = (const float*)d_in[8];
    const float* W_v    = (const float*)d_in[9];
    const float* b_v    = (const float*)d_in[10];
    float* out = (float*)d_out;

    float *xr, *WencR, *feats, *gates, *ys, *hT, *WiP, *bP, *Whd;
    unsigned* WhP;
    cudaGetSymbolAddress((void**)&xr,    g_xr);
    cudaGetSymbolAddress((void**)&WencR, g_WencR);
    cudaGetSymbolAddress((void**)&feats, g_feats);
    cudaGetSymbolAddress((void**)&gates, g_gates);
    cudaGetSymbolAddress((void**)&ys,    g_ys);
    cudaGetSymbolAddress((void**)&hT,    g_hT);
    cudaGetSymbolAddress((void**)&WiP,   g_WiP);
    cudaGetSymbolAddress((void**)&WhP,   g_WhP);
    cudaGetSymbolAddress((void**)&bP,    g_bP);
    cudaGetSymbolAddress((void**)&Whd,   g_Whd);

    static int attr_set = 0;
    if (!attr_set) {
        cudaFuncSetAttribute(lstm_persistent,
                             cudaFuncAttributeMaxDynamicSharedMemorySize, SMEM_LSTM);
        cudaFuncSetAttribute(gemm_mma,
                             cudaFuncAttributeMaxDynamicSharedMemorySize, SMEM_GEMM);
        attr_set = 1;
    }

    zero_kernel<<<(HT_ELEMS + 255) / 256, 256>>>(hT, HT_ELEMS);
    zero_bar4<<<1, 128>>>();

    round4_kernel<<<(ROWS * OBSD / 4 + 255) / 256, 256>>>(
        (const float4*)x, (float4*)xr, ROWS * OBSD / 4);
    round4_kernel<<<(OBSD * HIDD / 4 + 255) / 256, 256>>>(
        (const float4*)W_enc, (float4*)WencR, OBSD * HIDD / 4);
    permute_wi<<<(HIDD * GATES_N) / 256, 256>>>(W_i, WiP);
    permute_wh<<<(LSTMD * GATES_N) / 256, 256>>>(W_h, WhP);
    permute_b<<<(GATES_N + 255) / 256, 256>>>(b_lstm, bP);
    prep_whd<<<(LSTMD * 64) / 256, 256>>>(W_mu, W_v, Whd);

    {
        dim3 grid(HIDD / 128, ROWS / 128);
        gemm_mma<<<grid, 256, SMEM_GEMM>>>(xr, WencR, b_enc, feats,
                                           ROWS, HIDD, OBSD, 1, 1);
    }
    {
        dim3 grid(GATES_N / 128, ROWS / 128);
        gemm_mma<<<grid, 256, SMEM_GEMM>>>(feats, WiP, bP, gates,
                                           ROWS, GATES_N, HIDD, 0, 0);
    }
    {
        dim3 grid(32, 4);
        lstm_persistent<<<grid, 256, SMEM_LSTM>>>(WhP, gates, ys);
    }
    heads_mma<<<ROWS / 128, 256>>>(Whd, b_mu, logstd, b_v, out);
}